// round 1
// baseline (speedup 1.0000x reference)
#include <cuda_runtime.h>
#include <cuda_bf16.h>
#include <math.h>

// ---------------------------------------------------------------------------
// Problem constants (hardcoded per reference: B=8, H=W=128, C=192, WS=8, SHIFT=4)
// ---------------------------------------------------------------------------
#define BATCH   8
#define HH      128
#define WW_     128
#define LL      (HH*WW_)          // 16384
#define CC      192
#define HEADS   6
#define HD      32
#define WS      8
#define NWIN    64                // WS*WS
#define SHIFT   4
#define HIDDEN  768
#define MROWS   (BATCH*LL)        // 131072
#define NWINDOWS (BATCH*(HH/WS)*(WW_/WS))  // 2048
#define POS_DIM 12
#define POS_TAB 225               // (2*WS-1)^2

// ---------------------------------------------------------------------------
// Device scratch (static; allocation-free per harness rules)
// ---------------------------------------------------------------------------
__device__ float g_xw[(size_t)MROWS * CC];       // LN1 + shifted window layout
__device__ float g_qkv[(size_t)MROWS * 3 * CC];  // qkv in window layout
__device__ float g_attn[(size_t)MROWS * CC];     // attention output (window layout)
__device__ float g_ln2[(size_t)MROWS * CC];      // LN2 output
__device__ float g_hid[(size_t)MROWS * HIDDEN];  // MLP hidden
__device__ float g_pos[POS_TAB * HEADS];         // position bias table

// ---------------------------------------------------------------------------
// Position-bias MLP: 225 rows through 3 tiny LN+ReLU+Linear layers
// ---------------------------------------------------------------------------
__device__ __forceinline__ void ln_relu12(const float* p, float* q,
                                          const float* g, const float* b) {
    float s = 0.f, s2 = 0.f;
#pragma unroll
    for (int i = 0; i < POS_DIM; i++) { s += p[i]; s2 += p[i] * p[i]; }
    float mu = s / 12.0f;
    float var = s2 / 12.0f - mu * mu;
    float rs = rsqrtf(var + 1e-5f);
#pragma unroll
    for (int i = 0; i < POS_DIM; i++) {
        float u = (p[i] - mu) * rs * g[i] + b[i];
        q[i] = fmaxf(u, 0.0f);
    }
}

__global__ void pos_mlp_kernel(
    const float* __restrict__ pp_w, const float* __restrict__ pp_b,
    const float* __restrict__ p1_g, const float* __restrict__ p1_b,
    const float* __restrict__ p1_w, const float* __restrict__ p1_bias,
    const float* __restrict__ p2_g, const float* __restrict__ p2_b,
    const float* __restrict__ p2_w, const float* __restrict__ p2_bias,
    const float* __restrict__ p3_g, const float* __restrict__ p3_b,
    const float* __restrict__ p3_w, const float* __restrict__ p3_bias) {
    int t = blockIdx.x * blockDim.x + threadIdx.x;
    if (t >= POS_TAB) return;
    float bh = (float)(t / 15 - 7);
    float bw = (float)(t % 15 - 7);
    float p[POS_DIM], q[POS_DIM];
#pragma unroll
    for (int j = 0; j < POS_DIM; j++)
        p[j] = bh * pp_w[j] + bw * pp_w[POS_DIM + j] + pp_b[j];

    ln_relu12(p, q, p1_g, p1_b);
#pragma unroll
    for (int j = 0; j < POS_DIM; j++) {
        float s = p1_bias[j];
#pragma unroll
        for (int i = 0; i < POS_DIM; i++) s += q[i] * p1_w[i * POS_DIM + j];
        p[j] = s;
    }
    ln_relu12(p, q, p2_g, p2_b);
#pragma unroll
    for (int j = 0; j < POS_DIM; j++) {
        float s = p2_bias[j];
#pragma unroll
        for (int i = 0; i < POS_DIM; i++) s += q[i] * p2_w[i * POS_DIM + j];
        p[j] = s;
    }
    ln_relu12(p, q, p3_g, p3_b);
#pragma unroll
    for (int h = 0; h < HEADS; h++) {
        float s = p3_bias[h];
#pragma unroll
        for (int i = 0; i < POS_DIM; i++) s += q[i] * p3_w[i * HEADS + h];
        g_pos[t * HEADS + h] = s;
    }
}

// ---------------------------------------------------------------------------
// LayerNorm over C=192; one warp per row.
// mode 0: output row = window-layout row g; source = x at shifted image pos.
// mode 1: identity mapping.
// ---------------------------------------------------------------------------
__global__ void __launch_bounds__(256) ln_kernel(
    const float* __restrict__ in, float* __restrict__ out,
    const float* __restrict__ gamma, const float* __restrict__ beta, int mode) {
    int warp = threadIdx.x >> 5;
    int lane = threadIdx.x & 31;
    int row = blockIdx.x * 8 + warp;

    size_t src;
    if (mode == 0) {
        int bb = row >> 14;
        int rem = row & 16383;
        int win = rem >> 6;
        int r = rem & 63;
        int wy = win >> 4, wx = win & 15;
        int ry = r >> 3, rx = r & 7;
        int hh = (wy * WS + ry + SHIFT) & 127;
        int ww = (wx * WS + rx + SHIFT) & 127;
        src = (size_t)bb * LL + hh * WW_ + ww;
    } else {
        src = (size_t)row;
    }

    const float* p = in + src * CC;
    float v[6];
    float s = 0.f, s2 = 0.f;
#pragma unroll
    for (int k = 0; k < 6; k++) {
        v[k] = p[lane + 32 * k];
        s += v[k];
        s2 += v[k] * v[k];
    }
#pragma unroll
    for (int o = 16; o > 0; o >>= 1) {
        s += __shfl_xor_sync(0xFFFFFFFFu, s, o);
        s2 += __shfl_xor_sync(0xFFFFFFFFu, s2, o);
    }
    float mu = s * (1.0f / 192.0f);
    float var = s2 * (1.0f / 192.0f) - mu * mu;
    float rs = rsqrtf(var + 1e-5f);

    float* q = out + (size_t)row * CC;
#pragma unroll
    for (int k = 0; k < 6; k++) {
        int c = lane + 32 * k;
        q[c] = (v[k] - mu) * rs * gamma[c] + beta[c];
    }
}

// ---------------------------------------------------------------------------
// Generic fp32 SGEMM: out[M,N] = A[M,K] @ W[K,N] + bias, fused epilogues.
// 64x64 tile, BK=16, 256 threads, 4x4 per thread.
// EPI 0: plain + bias          (qkv -> g_qkv)
// EPI 1: bias + exact GELU     (fc1 -> g_hid)
// EPI 2: bias + window-reverse scatter + residual(x) (proj -> d_out = y)
// EPI 3: bias + residual(out)  (fc2 += y -> d_out)
// ---------------------------------------------------------------------------
__device__ __forceinline__ float gelu_exact(float x) {
    return 0.5f * x * (1.0f + erff(x * 0.7071067811865476f));
}

template <int EPI>
__global__ void __launch_bounds__(256) gemm_kernel(
    const float* __restrict__ A, const float* __restrict__ W,
    const float* __restrict__ bias, const float* __restrict__ res,
    float* __restrict__ out, int K, int N) {
    __shared__ float As[16][64];
    __shared__ float Bs[16][64];

    int tid = threadIdx.x;
    int tx = tid & 15, ty = tid >> 4;
    int m0 = blockIdx.y * 64, n0 = blockIdx.x * 64;

    float acc[4][4];
#pragma unroll
    for (int i = 0; i < 4; i++)
#pragma unroll
        for (int j = 0; j < 4; j++) acc[i][j] = 0.f;

    int la_m = tid >> 2;
    int la_k = (tid & 3) * 4;
    int lb_k = tid >> 4;
    int lb_n = (tid & 15) * 4;

    const float* Aptr = A + (size_t)(m0 + la_m) * K + la_k;
    const float* Wptr = W + (size_t)lb_k * N + n0 + lb_n;

    for (int k0 = 0; k0 < K; k0 += 16) {
        float4 av = *(const float4*)(Aptr + k0);
        float4 bv = *(const float4*)(Wptr + (size_t)k0 * N);
        __syncthreads();
        As[la_k + 0][la_m] = av.x;
        As[la_k + 1][la_m] = av.y;
        As[la_k + 2][la_m] = av.z;
        As[la_k + 3][la_m] = av.w;
        *(float4*)&Bs[lb_k][lb_n] = bv;
        __syncthreads();
#pragma unroll
        for (int k = 0; k < 16; k++) {
            float a[4], b[4];
#pragma unroll
            for (int i = 0; i < 4; i++) a[i] = As[k][ty * 4 + i];
#pragma unroll
            for (int j = 0; j < 4; j++) b[j] = Bs[k][tx * 4 + j];
#pragma unroll
            for (int i = 0; i < 4; i++)
#pragma unroll
                for (int j = 0; j < 4; j++) acc[i][j] += a[i] * b[j];
        }
    }

#pragma unroll
    for (int i = 0; i < 4; i++) {
        int g = m0 + ty * 4 + i;
        size_t obase;
        if (EPI == 2) {
            int bb = g >> 14;
            int rem = g & 16383;
            int win = rem >> 6;
            int r = rem & 63;
            int wy = win >> 4, wx = win & 15;
            int ry = r >> 3, rx = r & 7;
            int hh = (wy * WS + ry + SHIFT) & 127;
            int ww = (wx * WS + rx + SHIFT) & 127;
            obase = ((size_t)bb * LL + hh * WW_ + ww) * CC;
        } else {
            obase = (size_t)g * N;
        }
#pragma unroll
        for (int j = 0; j < 4; j++) {
            int col = n0 + tx * 4 + j;
            float v = acc[i][j] + bias[col];
            if (EPI == 1) v = gelu_exact(v);
            if (EPI == 2) v += res[obase + col];
            if (EPI == 3) v += res[obase + col];
            out[obase + col] = v;
        }
    }
}

// ---------------------------------------------------------------------------
// Windowed attention. One block per window (2048), 384 threads = (head, row).
// K/V staged in dynamic smem (2 * 64 * 192 * 4 = 96 KB). Two-pass softmax.
// ---------------------------------------------------------------------------
__global__ void __launch_bounds__(384) attn_kernel(
    const float* __restrict__ qkv, const float* __restrict__ pos,
    float* __restrict__ outp) {
    extern __shared__ float sm[];
    float* k_s = sm;                 // [64][192]
    float* v_s = sm + NWIN * CC;     // [64][192]

    int w = blockIdx.x;
    int tid = threadIdx.x;

    const float* base = qkv + (size_t)w * NWIN * (3 * CC);

    float4* k4 = (float4*)k_s;
    float4* v4 = (float4*)v_s;
    for (int idx = tid; idx < NWIN * 48; idx += 384) {
        int j = idx / 48, c = idx % 48;
        k4[j * 48 + c] = *(const float4*)(base + (size_t)j * 576 + 192 + c * 4);
        v4[j * 48 + c] = *(const float4*)(base + (size_t)j * 576 + 384 + c * 4);
    }
    __syncthreads();

    int h = tid / NWIN;
    int r = tid % NWIN;
    int ry = r >> 3, rx = r & 7;
    int winloc = w & 255;
    int wy = winloc >> 4, wx = winloc & 15;

    int lh_r = (wy == 15) ? (ry < (WS - SHIFT) ? 1 : 2) : 0;
    int lw_r = (wx == 15) ? (rx < (WS - SHIFT) ? 1 : 2) : 0;

    float q[HD];
    const float* qp = base + (size_t)r * 576 + h * HD;
#pragma unroll
    for (int d = 0; d < HD; d++) q[d] = qp[d] * 0.17677669529663687f;  // 32^-0.5

    const float* ks = k_s + h * HD;
    const float* vs = v_s + h * HD;

    // pass 1: row max
    float mx = -1e30f;
    for (int j = 0; j < NWIN; j++) {
        float s = 0.f;
        const float* kj = ks + j * CC;
#pragma unroll
        for (int d = 0; d < HD; d++) s += q[d] * kj[d];
        int jy = j >> 3, jx = j & 7;
        s += pos[(((ry - jy + 7) * 15) + (rx - jx + 7)) * HEADS + h];
        int lh_j = (wy == 15) ? (jy < (WS - SHIFT) ? 1 : 2) : 0;
        int lw_j = (wx == 15) ? (jx < (WS - SHIFT) ? 1 : 2) : 0;
        if (lh_j != lh_r || lw_j != lw_r) s -= 100.0f;
        mx = fmaxf(mx, s);
    }

    // pass 2: exp-sum + weighted V
    float sum = 0.f;
    float acc[HD];
#pragma unroll
    for (int d = 0; d < HD; d++) acc[d] = 0.f;

    for (int j = 0; j < NWIN; j++) {
        float s = 0.f;
        const float* kj = ks + j * CC;
#pragma unroll
        for (int d = 0; d < HD; d++) s += q[d] * kj[d];
        int jy = j >> 3, jx = j & 7;
        s += pos[(((ry - jy + 7) * 15) + (rx - jx + 7)) * HEADS + h];
        int lh_j = (wy == 15) ? (jy < (WS - SHIFT) ? 1 : 2) : 0;
        int lw_j = (wx == 15) ? (jx < (WS - SHIFT) ? 1 : 2) : 0;
        if (lh_j != lh_r || lw_j != lw_r) s -= 100.0f;

        float p = expf(s - mx);
        sum += p;
        const float* vj = vs + j * CC;
#pragma unroll
        for (int d = 0; d < HD; d++) acc[d] += p * vj[d];
    }

    float inv = 1.0f / sum;
    float* op = outp + (size_t)(w * NWIN + r) * CC + h * HD;
#pragma unroll
    for (int d = 0; d < HD; d++) op[d] = acc[d] * inv;
}

// ---------------------------------------------------------------------------
// Launch
// ---------------------------------------------------------------------------
extern "C" void kernel_launch(void* const* d_in, const int* in_sizes, int n_in,
                              void* d_out, int out_size) {
    const float* x      = (const float*)d_in[0];
    // d_in[1] = k_v (unused), d_in[2] = H, d_in[3] = W (static 128)
    const float* n1_g   = (const float*)d_in[4];
    const float* n1_b   = (const float*)d_in[5];
    const float* qkv_w  = (const float*)d_in[6];
    const float* qkv_b  = (const float*)d_in[7];
    const float* proj_w = (const float*)d_in[8];
    const float* proj_b = (const float*)d_in[9];
    const float* pp_w   = (const float*)d_in[10];
    const float* pp_b   = (const float*)d_in[11];
    const float* p1_g   = (const float*)d_in[12];
    const float* p1_b   = (const float*)d_in[13];
    const float* p1_w   = (const float*)d_in[14];
    const float* p1_bi  = (const float*)d_in[15];
    const float* p2_g   = (const float*)d_in[16];
    const float* p2_b   = (const float*)d_in[17];
    const float* p2_w   = (const float*)d_in[18];
    const float* p2_bi  = (const float*)d_in[19];
    const float* p3_g   = (const float*)d_in[20];
    const float* p3_b   = (const float*)d_in[21];
    const float* p3_w   = (const float*)d_in[22];
    const float* p3_bi  = (const float*)d_in[23];
    const float* n2_g   = (const float*)d_in[24];
    const float* n2_b   = (const float*)d_in[25];
    const float* fc1_w  = (const float*)d_in[26];
    const float* fc1_b  = (const float*)d_in[27];
    const float* fc2_w  = (const float*)d_in[28];
    const float* fc2_b  = (const float*)d_in[29];
    float* out = (float*)d_out;

    float *xw, *qkv, *attn, *ln2, *hid, *pos;
    cudaGetSymbolAddress((void**)&xw,   g_xw);
    cudaGetSymbolAddress((void**)&qkv,  g_qkv);
    cudaGetSymbolAddress((void**)&attn, g_attn);
    cudaGetSymbolAddress((void**)&ln2,  g_ln2);
    cudaGetSymbolAddress((void**)&hid,  g_hid);
    cudaGetSymbolAddress((void**)&pos,  g_pos);

    // 1. position-bias MLP table
    pos_mlp_kernel<<<1, 256>>>(pp_w, pp_b, p1_g, p1_b, p1_w, p1_bi,
                               p2_g, p2_b, p2_w, p2_bi, p3_g, p3_b, p3_w, p3_bi);

    // 2. LN1 + shift + window partition
    ln_kernel<<<MROWS / 8, 256>>>(x, xw, n1_g, n1_b, 0);

    // 3. QKV GEMM [131072,192]x[192,576]
    gemm_kernel<0><<<dim3(576 / 64, MROWS / 64), 256>>>(xw, qkv_w, qkv_b, nullptr, qkv, CC, 576);

    // 4. windowed attention
    static bool attr_set = false;
    if (!attr_set) {
        cudaFuncSetAttribute(attn_kernel, cudaFuncAttributeMaxDynamicSharedMemorySize,
                             2 * NWIN * CC * sizeof(float));
        attr_set = true;
    }
    attn_kernel<<<NWINDOWS, 384, 2 * NWIN * CC * sizeof(float)>>>(qkv, pos, attn);

    // 5. proj GEMM + window-reverse + unshift + residual(x) -> out = y
    gemm_kernel<2><<<dim3(CC / 64, MROWS / 64), 256>>>(attn, proj_w, proj_b, x, out, CC, CC);

    // 6. LN2 on y
    ln_kernel<<<MROWS / 8, 256>>>(out, ln2, n2_g, n2_b, 1);

    // 7. FC1 + exact GELU
    gemm_kernel<1><<<dim3(HIDDEN / 64, MROWS / 64), 256>>>(ln2, fc1_w, fc1_b, nullptr, hid, CC, HIDDEN);

    // 8. FC2 + residual(y) -> out
    gemm_kernel<3><<<dim3(CC / 64, MROWS / 64), 256>>>(hid, fc2_w, fc2_b, out, out, HIDDEN, CC);
}

// round 3
// speedup vs baseline: 2.7266x; 2.7266x over previous
#include <cuda_runtime.h>
#include <cuda_bf16.h>
#include <math.h>
#include <stdint.h>

// ---------------------------------------------------------------------------
// Problem constants
// ---------------------------------------------------------------------------
#define BATCH   8
#define HH      128
#define WW_     128
#define LL      (HH*WW_)
#define CC      192
#define HEADS   6
#define HD      32
#define WS      8
#define NWIN    64
#define SHIFT   4
#define HIDDEN  768
#define MROWS   (BATCH*LL)                 // 131072
#define NWINDOWS (BATCH*(HH/WS)*(WW_/WS))  // 2048
#define POS_DIM 12
#define POS_TAB 225

// ---------------------------------------------------------------------------
// Device scratch
// ---------------------------------------------------------------------------
__device__ float g_xw[(size_t)MROWS * CC];
__device__ float g_qkv[(size_t)MROWS * 3 * CC];
__device__ float g_attn[(size_t)MROWS * CC];
__device__ float g_ln2[(size_t)MROWS * CC];
__device__ float g_hid[(size_t)MROWS * HIDDEN];
__device__ float g_pos[POS_TAB * HEADS];
__device__ float g_wt_qkv[3 * CC * CC];
__device__ float g_wt_proj[CC * CC];
__device__ float g_wt_fc1[HIDDEN * CC];
__device__ float g_wt_fc2[CC * HIDDEN];

// ---------------------------------------------------------------------------
// Helpers
// ---------------------------------------------------------------------------
__device__ __forceinline__ float rtf32(float x) {
    uint32_t u;
    asm("cvt.rna.tf32.f32 %0, %1;" : "=r"(u) : "f"(x));
    return __uint_as_float(u);
}
__device__ __forceinline__ uint32_t smem_u32(const void* p) {
    uint32_t a;
    asm("{ .reg .u64 t; cvta.to.shared.u64 t, %1; cvt.u32.u64 %0, t; }" : "=r"(a) : "l"(p));
    return a;
}
__device__ __forceinline__ void cpasync16(uint32_t s, const void* g) {
    asm volatile("cp.async.cg.shared.global [%0], [%1], 16;" :: "r"(s), "l"(g));
}
__device__ __forceinline__ void cp_commit() {
    asm volatile("cp.async.commit_group;" ::: "memory");
}
__device__ __forceinline__ void cp_wait1() {
    asm volatile("cp.async.wait_group 1;" ::: "memory");
}
__device__ __forceinline__ void mma_tf32(float* d, const uint32_t* a, const uint32_t* b) {
    asm volatile(
        "mma.sync.aligned.m16n8k8.row.col.f32.tf32.tf32.f32 "
        "{%0,%1,%2,%3}, {%4,%5,%6,%7}, {%8,%9}, {%0,%1,%2,%3};"
        : "+f"(d[0]), "+f"(d[1]), "+f"(d[2]), "+f"(d[3])
        : "r"(a[0]), "r"(a[1]), "r"(a[2]), "r"(a[3]), "r"(b[0]), "r"(b[1]));
}
__device__ __forceinline__ float gelu_exact(float x) {
    return 0.5f * x * (1.0f + erff(x * 0.7071067811865476f));
}

// ---------------------------------------------------------------------------
// Weight transpose (W[K,N] -> WT[N,K]) with tf32 rounding
// ---------------------------------------------------------------------------
__global__ void transpose_w(const float* __restrict__ w, float* __restrict__ wt, int K, int N) {
    int i = blockIdx.x * 256 + threadIdx.x;
    if (i >= K * N) return;
    int k = i / N, n = i % N;
    wt[(size_t)n * K + k] = rtf32(w[i]);
}

// ---------------------------------------------------------------------------
// Position-bias MLP
// ---------------------------------------------------------------------------
__device__ __forceinline__ void ln_relu12(const float* p, float* q,
                                          const float* g, const float* b) {
    float s = 0.f, s2 = 0.f;
#pragma unroll
    for (int i = 0; i < POS_DIM; i++) { s += p[i]; s2 += p[i] * p[i]; }
    float mu = s / 12.0f;
    float var = s2 / 12.0f - mu * mu;
    float rs = rsqrtf(var + 1e-5f);
#pragma unroll
    for (int i = 0; i < POS_DIM; i++) q[i] = fmaxf((p[i] - mu) * rs * g[i] + b[i], 0.0f);
}

__global__ void pos_mlp_kernel(
    const float* __restrict__ pp_w, const float* __restrict__ pp_b,
    const float* __restrict__ p1_g, const float* __restrict__ p1_b,
    const float* __restrict__ p1_w, const float* __restrict__ p1_bias,
    const float* __restrict__ p2_g, const float* __restrict__ p2_b,
    const float* __restrict__ p2_w, const float* __restrict__ p2_bias,
    const float* __restrict__ p3_g, const float* __restrict__ p3_b,
    const float* __restrict__ p3_w, const float* __restrict__ p3_bias) {
    int t = blockIdx.x * blockDim.x + threadIdx.x;
    if (t >= POS_TAB) return;
    float bh = (float)(t / 15 - 7), bw = (float)(t % 15 - 7);
    float p[POS_DIM], q[POS_DIM];
#pragma unroll
    for (int j = 0; j < POS_DIM; j++) p[j] = bh * pp_w[j] + bw * pp_w[POS_DIM + j] + pp_b[j];
    ln_relu12(p, q, p1_g, p1_b);
#pragma unroll
    for (int j = 0; j < POS_DIM; j++) {
        float s = p1_bias[j];
#pragma unroll
        for (int i = 0; i < POS_DIM; i++) s += q[i] * p1_w[i * POS_DIM + j];
        p[j] = s;
    }
    ln_relu12(p, q, p2_g, p2_b);
#pragma unroll
    for (int j = 0; j < POS_DIM; j++) {
        float s = p2_bias[j];
#pragma unroll
        for (int i = 0; i < POS_DIM; i++) s += q[i] * p2_w[i * POS_DIM + j];
        p[j] = s;
    }
    ln_relu12(p, q, p3_g, p3_b);
#pragma unroll
    for (int h = 0; h < HEADS; h++) {
        float s = p3_bias[h];
#pragma unroll
        for (int i = 0; i < POS_DIM; i++) s += q[i] * p3_w[i * HEADS + h];
        g_pos[t * HEADS + h] = s;
    }
}

// ---------------------------------------------------------------------------
// LayerNorm (C=192), warp per row, tf32-rounded output (feeds GEMMs).
// mode 0: shift+window gather; mode 1: identity
// ---------------------------------------------------------------------------
__global__ void __launch_bounds__(256) ln_kernel(
    const float* __restrict__ in, float* __restrict__ out,
    const float* __restrict__ gamma, const float* __restrict__ beta, int mode) {
    int warp = threadIdx.x >> 5, lane = threadIdx.x & 31;
    int row = blockIdx.x * 8 + warp;
    size_t src;
    if (mode == 0) {
        int bb = row >> 14, rem = row & 16383;
        int win = rem >> 6, r = rem & 63;
        int wy = win >> 4, wx = win & 15, ry = r >> 3, rx = r & 7;
        int hh = (wy * WS + ry + SHIFT) & 127;
        int ww = (wx * WS + rx + SHIFT) & 127;
        src = (size_t)bb * LL + hh * WW_ + ww;
    } else src = (size_t)row;

    const float* p = in + src * CC;
    float v[6], s = 0.f, s2 = 0.f;
#pragma unroll
    for (int k = 0; k < 6; k++) { v[k] = p[lane + 32 * k]; s += v[k]; s2 += v[k] * v[k]; }
#pragma unroll
    for (int o = 16; o > 0; o >>= 1) {
        s += __shfl_xor_sync(0xFFFFFFFFu, s, o);
        s2 += __shfl_xor_sync(0xFFFFFFFFu, s2, o);
    }
    float mu = s * (1.0f / 192.0f);
    float rs = rsqrtf(s2 * (1.0f / 192.0f) - mu * mu + 1e-5f);
    float* q = out + (size_t)row * CC;
#pragma unroll
    for (int k = 0; k < 6; k++) {
        int c = lane + 32 * k;
        q[c] = rtf32((v[k] - mu) * rs * gamma[c] + beta[c]);
    }
}

// ---------------------------------------------------------------------------
// tf32 mma.sync GEMM: out[M,NOUT], 128x64 block tile, BK=32, cp.async x2 buf.
// A[M,K] row-major (tf32-rounded), BT[N,K] row-major (tf32-rounded).
// 8 warps: warp_m = wid&3 (32 rows), warp_n = wid>>2 (32 cols).
// EPI 0: +bias   1: gelu(+bias), rounded   2: +bias, scatter+res   3: +bias+res
// ---------------------------------------------------------------------------
#define AST 36
#define ABUF_F (192*AST)      // floats per buffer (A 128 rows + B 64 rows)
#define GEMM_SMEM (2*ABUF_F*4)

template <int EPI>
__global__ void __launch_bounds__(256) gemm_mma(
    const float* __restrict__ A, const float* __restrict__ BT,
    const float* __restrict__ bias, const float* __restrict__ res,
    float* __restrict__ out, int K, int NOUT) {
    extern __shared__ float smf[];
    uint32_t sbase = smem_u32(smf);
    int tid = threadIdx.x;
    int wid = tid >> 5, lane = tid & 31;
    int wm = wid & 3, wn = wid >> 2;
    int m0 = blockIdx.y * 128, n0 = blockIdx.x * 64;
    const float* Ab = A + (size_t)m0 * K;
    const float* Bb = BT + (size_t)n0 * K;
    int NCH = K >> 5;

    float acc[2][4][4];
#pragma unroll
    for (int i = 0; i < 2; i++)
#pragma unroll
        for (int j = 0; j < 4; j++)
#pragma unroll
            for (int k = 0; k < 4; k++) acc[i][j][k] = 0.f;

    int la_row = tid >> 3, la_seg = tid & 7;

    // prologue: chunk 0
    {
        uint32_t dst = sbase;
#pragma unroll
        for (int i = 0; i < 4; i++) {
            int row = la_row + i * 32;
            cpasync16(dst + (row * AST + la_seg * 4) * 4, Ab + (size_t)row * K + la_seg * 4);
        }
#pragma unroll
        for (int i = 0; i < 2; i++) {
            int row = la_row + i * 32;
            cpasync16(dst + ((128 + row) * AST + la_seg * 4) * 4, Bb + (size_t)row * K + la_seg * 4);
        }
        cp_commit();
    }

    for (int c = 0; c < NCH; c++) {
        if (c + 1 < NCH) {
            int k0 = (c + 1) << 5;
            uint32_t dst = sbase + ((c + 1) & 1) * ABUF_F * 4;
#pragma unroll
            for (int i = 0; i < 4; i++) {
                int row = la_row + i * 32;
                cpasync16(dst + (row * AST + la_seg * 4) * 4, Ab + (size_t)row * K + k0 + la_seg * 4);
            }
#pragma unroll
            for (int i = 0; i < 2; i++) {
                int row = la_row + i * 32;
                cpasync16(dst + ((128 + row) * AST + la_seg * 4) * 4, Bb + (size_t)row * K + k0 + la_seg * 4);
            }
        }
        cp_commit();
        cp_wait1();
        __syncthreads();

        const float* As = smf + (c & 1) * ABUF_F;
        const float* Bs = As + 128 * AST;
        const float* ap0 = As + (wm * 32 + (lane >> 2)) * AST + (lane & 3);
        const float* bp0 = Bs + (wn * 32 + (lane >> 2)) * AST + (lane & 3);

#pragma unroll
        for (int ks = 0; ks < 4; ks++) {
            int k0s = ks * 8;
            uint32_t a[2][4], b[4][2];
#pragma unroll
            for (int mt = 0; mt < 2; mt++) {
                const float* ap = ap0 + mt * 16 * AST + k0s;
                a[mt][0] = __float_as_uint(ap[0]);
                a[mt][1] = __float_as_uint(ap[8 * AST]);
                a[mt][2] = __float_as_uint(ap[4]);
                a[mt][3] = __float_as_uint(ap[8 * AST + 4]);
            }
#pragma unroll
            for (int nt = 0; nt < 4; nt++) {
                const float* bp = bp0 + nt * 8 * AST + k0s;
                b[nt][0] = __float_as_uint(bp[0]);
                b[nt][1] = __float_as_uint(bp[4]);
            }
#pragma unroll
            for (int mt = 0; mt < 2; mt++)
#pragma unroll
                for (int nt = 0; nt < 4; nt++)
                    mma_tf32(acc[mt][nt], a[mt], b[nt]);
        }
        __syncthreads();
    }

    // epilogue: c0,c1 at (row, 2c/2c+1); c2,c3 at (row+8)
#pragma unroll
    for (int mt = 0; mt < 2; mt++) {
        int g0 = m0 + wm * 32 + mt * 16 + (lane >> 2);
        int g1 = g0 + 8;
        size_t ob0, ob1;
        if (EPI == 2) {
#pragma unroll
            for (int half = 0; half < 2; half++) {
                int g = half ? g1 : g0;
                int bb = g >> 14, rem = g & 16383;
                int win = rem >> 6, rr = rem & 63;
                int wy = win >> 4, wx = win & 15, ry = rr >> 3, rx = rr & 7;
                int hh = (wy * WS + ry + SHIFT) & 127;
                int ww = (wx * WS + rx + SHIFT) & 127;
                size_t ob = ((size_t)bb * LL + hh * WW_ + ww) * CC;
                if (half) ob1 = ob; else ob0 = ob;
            }
        } else {
            ob0 = (size_t)g0 * NOUT;
            ob1 = (size_t)g1 * NOUT;
        }
#pragma unroll
        for (int nt = 0; nt < 4; nt++) {
            int col = n0 + wn * 32 + nt * 8 + 2 * (lane & 3);
            float b0 = bias[col], b1 = bias[col + 1];
            float2 v0 = make_float2(acc[mt][nt][0] + b0, acc[mt][nt][1] + b1);
            float2 v1 = make_float2(acc[mt][nt][2] + b0, acc[mt][nt][3] + b1);
            if (EPI == 1) {
                v0.x = rtf32(gelu_exact(v0.x)); v0.y = rtf32(gelu_exact(v0.y));
                v1.x = rtf32(gelu_exact(v1.x)); v1.y = rtf32(gelu_exact(v1.y));
            }
            if (EPI == 2 || EPI == 3) {
                float2 r0 = *(const float2*)(res + ob0 + col);
                float2 r1 = *(const float2*)(res + ob1 + col);
                v0.x += r0.x; v0.y += r0.y;
                v1.x += r1.x; v1.y += r1.y;
            }
            *(float2*)(out + ob0 + col) = v0;
            *(float2*)(out + ob1 + col) = v1;
        }
    }
}

// ---------------------------------------------------------------------------
// Windowed attention: online softmax, float4 smem, 384 thr/window.
// Output tf32-rounded (feeds proj GEMM).
// ---------------------------------------------------------------------------
__global__ void __launch_bounds__(384) attn_kernel(
    const float* __restrict__ qkv, const float* __restrict__ pos,
    float* __restrict__ outp) {
    extern __shared__ float smf[];
    float* k_s = smf;
    float* v_s = smf + NWIN * CC;

    int w = blockIdx.x;
    int tid = threadIdx.x;
    const float* base = qkv + (size_t)w * NWIN * (3 * CC);

    float4* k4 = (float4*)k_s;
    float4* v4 = (float4*)v_s;
    for (int idx = tid; idx < NWIN * 48; idx += 384) {
        int j = idx / 48, c = idx % 48;
        k4[j * 48 + c] = *(const float4*)(base + (size_t)j * 576 + 192 + c * 4);
        v4[j * 48 + c] = *(const float4*)(base + (size_t)j * 576 + 384 + c * 4);
    }
    __syncthreads();

    int h = tid / NWIN;
    int r = tid % NWIN;
    int ry = r >> 3, rx = r & 7;
    int winloc = w & 255;
    int wy = winloc >> 4, wx = winloc & 15;
    int lh_r = (wy == 15) ? (ry < (WS - SHIFT) ? 1 : 2) : 0;
    int lw_r = (wx == 15) ? (rx < (WS - SHIFT) ? 1 : 2) : 0;

    float4 q4[8];
    const float4* qp = (const float4*)(base + (size_t)r * 576 + h * HD);
#pragma unroll
    for (int d = 0; d < 8; d++) {
        q4[d] = qp[d];
        q4[d].x *= 0.17677669529663687f; q4[d].y *= 0.17677669529663687f;
        q4[d].z *= 0.17677669529663687f; q4[d].w *= 0.17677669529663687f;
    }

    const float* pb = pos + (((ry + 7) * 15) + (rx + 7)) * HEADS + h;
    const float4* ks = (const float4*)(k_s + h * HD);
    const float4* vs = (const float4*)(v_s + h * HD);

    float mx = -1e30f, sum = 0.f;
    float4 a4[8];
#pragma unroll
    for (int d = 0; d < 8; d++) a4[d] = make_float4(0.f, 0.f, 0.f, 0.f);

    for (int jy = 0; jy < 8; jy++) {
        int lh_j = (wy == 15) ? (jy < (WS - SHIFT) ? 1 : 2) : 0;
        bool hbad = (lh_j != lh_r);
        const float* pby = pb - jy * 90;
#pragma unroll
        for (int jx = 0; jx < 8; jx++) {
            int j = jy * 8 + jx;
            const float4* kj = ks + j * 48;
            float s0 = 0.f, s1 = 0.f, s2 = 0.f, s3 = 0.f;
#pragma unroll
            for (int d = 0; d < 8; d++) {
                float4 kv = kj[d];
                s0 += q4[d].x * kv.x; s1 += q4[d].y * kv.y;
                s2 += q4[d].z * kv.z; s3 += q4[d].w * kv.w;
            }
            float s = (s0 + s1) + (s2 + s3);
            s += pby[-(jx * 6)];
            int lw_j = (wx == 15) ? (jx < (WS - SHIFT) ? 1 : 2) : 0;
            if (hbad || (lw_j != lw_r)) s -= 100.0f;

            float p;
            if (s > mx) {
                float cr = __expf(mx - s);
                mx = s;
                sum *= cr;
#pragma unroll
                for (int d = 0; d < 8; d++) {
                    a4[d].x *= cr; a4[d].y *= cr; a4[d].z *= cr; a4[d].w *= cr;
                }
                p = 1.0f;
            } else {
                p = __expf(s - mx);
            }
            sum += p;
            const float4* vj = vs + j * 48;
#pragma unroll
            for (int d = 0; d < 8; d++) {
                float4 vv = vj[d];
                a4[d].x += p * vv.x; a4[d].y += p * vv.y;
                a4[d].z += p * vv.z; a4[d].w += p * vv.w;
            }
        }
    }

    float inv = 1.0f / sum;
    float4* op = (float4*)(outp + (size_t)(w * NWIN + r) * CC + h * HD);
#pragma unroll
    for (int d = 0; d < 8; d++) {
        float4 o;
        o.x = rtf32(a4[d].x * inv); o.y = rtf32(a4[d].y * inv);
        o.z = rtf32(a4[d].z * inv); o.w = rtf32(a4[d].w * inv);
        op[d] = o;
    }
}

// ---------------------------------------------------------------------------
// Launch
// ---------------------------------------------------------------------------
extern "C" void kernel_launch(void* const* d_in, const int* in_sizes, int n_in,
                              void* d_out, int out_size) {
    const float* x      = (const float*)d_in[0];
    const float* n1_g   = (const float*)d_in[4];
    const float* n1_b   = (const float*)d_in[5];
    const float* qkv_w  = (const float*)d_in[6];
    const float* qkv_b  = (const float*)d_in[7];
    const float* proj_w = (const float*)d_in[8];
    const float* proj_b = (const float*)d_in[9];
    const float* pp_w   = (const float*)d_in[10];
    const float* pp_b   = (const float*)d_in[11];
    const float* p1_g   = (const float*)d_in[12];
    const float* p1_b   = (const float*)d_in[13];
    const float* p1_w   = (const float*)d_in[14];
    const float* p1_bi  = (const float*)d_in[15];
    const float* p2_g   = (const float*)d_in[16];
    const float* p2_b   = (const float*)d_in[17];
    const float* p2_w   = (const float*)d_in[18];
    const float* p2_bi  = (const float*)d_in[19];
    const float* p3_g   = (const float*)d_in[20];
    const float* p3_b   = (const float*)d_in[21];
    const float* p3_w   = (const float*)d_in[22];
    const float* p3_bi  = (const float*)d_in[23];
    const float* n2_g   = (const float*)d_in[24];
    const float* n2_b   = (const float*)d_in[25];
    const float* fc1_w  = (const float*)d_in[26];
    const float* fc1_b  = (const float*)d_in[27];
    const float* fc2_w  = (const float*)d_in[28];
    const float* fc2_b  = (const float*)d_in[29];
    float* out = (float*)d_out;

    float *xw, *qkv, *attn, *ln2, *hid, *pos;
    float *wt_qkv, *wt_proj, *wt_fc1, *wt_fc2;
    cudaGetSymbolAddress((void**)&xw,   g_xw);
    cudaGetSymbolAddress((void**)&qkv,  g_qkv);
    cudaGetSymbolAddress((void**)&attn, g_attn);
    cudaGetSymbolAddress((void**)&ln2,  g_ln2);
    cudaGetSymbolAddress((void**)&hid,  g_hid);
    cudaGetSymbolAddress((void**)&pos,  g_pos);
    cudaGetSymbolAddress((void**)&wt_qkv,  g_wt_qkv);
    cudaGetSymbolAddress((void**)&wt_proj, g_wt_proj);
    cudaGetSymbolAddress((void**)&wt_fc1,  g_wt_fc1);
    cudaGetSymbolAddress((void**)&wt_fc2,  g_wt_fc2);

    static bool attr_set = false;
    if (!attr_set) {
        cudaFuncSetAttribute(attn_kernel, cudaFuncAttributeMaxDynamicSharedMemorySize,
                             2 * NWIN * CC * sizeof(float));
        cudaFuncSetAttribute(gemm_mma<0>, cudaFuncAttributeMaxDynamicSharedMemorySize, GEMM_SMEM);
        cudaFuncSetAttribute(gemm_mma<1>, cudaFuncAttributeMaxDynamicSharedMemorySize, GEMM_SMEM);
        cudaFuncSetAttribute(gemm_mma<2>, cudaFuncAttributeMaxDynamicSharedMemorySize, GEMM_SMEM);
        cudaFuncSetAttribute(gemm_mma<3>, cudaFuncAttributeMaxDynamicSharedMemorySize, GEMM_SMEM);
        attr_set = true;
    }

    // 0. weight transposes (tf32-rounded)
    transpose_w<<<(3 * CC * CC + 255) / 256, 256>>>(qkv_w, wt_qkv, CC, 3 * CC);
    transpose_w<<<(CC * CC + 255) / 256, 256>>>(proj_w, wt_proj, CC, CC);
    transpose_w<<<(CC * HIDDEN + 255) / 256, 256>>>(fc1_w, wt_fc1, CC, HIDDEN);
    transpose_w<<<(HIDDEN * CC + 255) / 256, 256>>>(fc2_w, wt_fc2, HIDDEN, CC);

    // 1. position-bias MLP
    pos_mlp_kernel<<<1, 256>>>(pp_w, pp_b, p1_g, p1_b, p1_w, p1_bi,
                               p2_g, p2_b, p2_w, p2_bi, p3_g, p3_b, p3_w, p3_bi);

    // 2. LN1 + shift + window partition (tf32-rounded)
    ln_kernel<<<MROWS / 8, 256>>>(x, xw, n1_g, n1_b, 0);

    // 3. QKV GEMM [131072,192] x [192,576]
    gemm_mma<0><<<dim3(576 / 64, MROWS / 128), 256, GEMM_SMEM>>>(xw, wt_qkv, qkv_b, nullptr, qkv, CC, 576);

    // 4. attention
    attn_kernel<<<NWINDOWS, 384, 2 * NWIN * CC * sizeof(float)>>>(qkv, pos, attn);

    // 5. proj + window-reverse + residual -> y
    gemm_mma<2><<<dim3(CC / 64, MROWS / 128), 256, GEMM_SMEM>>>(attn, wt_proj, proj_b, x, out, CC, CC);

    // 6. LN2 (tf32-rounded)
    ln_kernel<<<MROWS / 8, 256>>>(out, ln2, n2_g, n2_b, 1);

    // 7. FC1 + GELU (rounded output feeds FC2)
    gemm_mma<1><<<dim3(HIDDEN / 64, MROWS / 128), 256, GEMM_SMEM>>>(ln2, wt_fc1, fc1_b, nullptr, hid, CC, HIDDEN);

    // 8. FC2 + residual -> out
    gemm_mma<3><<<dim3(CC / 64, MROWS / 128), 256, GEMM_SMEM>>>(hid, wt_fc2, fc2_b, out, out, HIDDEN, CC);
}

// round 4
// speedup vs baseline: 3.2498x; 1.1919x over previous
#include <cuda_runtime.h>
#include <cuda_bf16.h>
#include <math.h>
#include <stdint.h>

// ---------------------------------------------------------------------------
// Problem constants
// ---------------------------------------------------------------------------
#define BATCH   8
#define HH      128
#define WW_     128
#define LL      (HH*WW_)
#define CC      192
#define HEADS   6
#define HD      32
#define WS      8
#define NWIN    64
#define SHIFT   4
#define HIDDEN  768
#define MROWS   (BATCH*LL)                 // 131072
#define NWINDOWS (BATCH*(HH/WS)*(WW_/WS))  // 2048
#define POS_DIM 12
#define POS_TAB 225

// ---------------------------------------------------------------------------
// Device scratch (bf16 activations, fp32 residual stream)
// ---------------------------------------------------------------------------
__device__ __nv_bfloat16 gb_xw[(size_t)MROWS * CC];
__device__ __nv_bfloat16 gb_qkv[(size_t)MROWS * 3 * CC];
__device__ __nv_bfloat16 gb_attn[(size_t)MROWS * CC];
__device__ __nv_bfloat16 gb_ln2[(size_t)MROWS * CC];
__device__ __nv_bfloat16 gb_hid[(size_t)MROWS * HIDDEN];
__device__ float g_pos[POS_TAB * HEADS];
__device__ __nv_bfloat16 gb_wt_qkv[3 * CC * CC];
__device__ __nv_bfloat16 gb_wt_proj[CC * CC];
__device__ __nv_bfloat16 gb_wt_fc1[HIDDEN * CC];
__device__ __nv_bfloat16 gb_wt_fc2[CC * HIDDEN];

// ---------------------------------------------------------------------------
// Helpers
// ---------------------------------------------------------------------------
__device__ __forceinline__ uint32_t smem_u32(const void* p) {
    uint32_t a;
    asm("{ .reg .u64 t; cvta.to.shared.u64 t, %1; cvt.u32.u64 %0, t; }" : "=r"(a) : "l"(p));
    return a;
}
__device__ __forceinline__ void cpasync16(uint32_t s, const void* g) {
    asm volatile("cp.async.cg.shared.global [%0], [%1], 16;" :: "r"(s), "l"(g));
}
__device__ __forceinline__ void cp_commit() {
    asm volatile("cp.async.commit_group;" ::: "memory");
}
__device__ __forceinline__ void cp_wait1() {
    asm volatile("cp.async.wait_group 1;" ::: "memory");
}
__device__ __forceinline__ void mma_bf16(float* d, const uint32_t* a, const uint32_t* b) {
    asm volatile(
        "mma.sync.aligned.m16n8k16.row.col.f32.bf16.bf16.f32 "
        "{%0,%1,%2,%3}, {%4,%5,%6,%7}, {%8,%9}, {%0,%1,%2,%3};"
        : "+f"(d[0]), "+f"(d[1]), "+f"(d[2]), "+f"(d[3])
        : "r"(a[0]), "r"(a[1]), "r"(a[2]), "r"(a[3]), "r"(b[0]), "r"(b[1]));
}
__device__ __forceinline__ float gelu_exact(float x) {
    return 0.5f * x * (1.0f + erff(x * 0.7071067811865476f));
}

// ---------------------------------------------------------------------------
// Weight transpose (W[K,N] -> WT[N,K]) with bf16 rounding
// ---------------------------------------------------------------------------
__global__ void transpose_w(const float* __restrict__ w, __nv_bfloat16* __restrict__ wt,
                            int K, int N) {
    int i = blockIdx.x * 256 + threadIdx.x;
    if (i >= K * N) return;
    int k = i / N, n = i % N;
    wt[(size_t)n * K + k] = __float2bfloat16(w[i]);
}

// ---------------------------------------------------------------------------
// Position-bias MLP
// ---------------------------------------------------------------------------
__device__ __forceinline__ void ln_relu12(const float* p, float* q,
                                          const float* g, const float* b) {
    float s = 0.f, s2 = 0.f;
#pragma unroll
    for (int i = 0; i < POS_DIM; i++) { s += p[i]; s2 += p[i] * p[i]; }
    float mu = s / 12.0f;
    float var = s2 / 12.0f - mu * mu;
    float rs = rsqrtf(var + 1e-5f);
#pragma unroll
    for (int i = 0; i < POS_DIM; i++) q[i] = fmaxf((p[i] - mu) * rs * g[i] + b[i], 0.0f);
}

__global__ void pos_mlp_kernel(
    const float* __restrict__ pp_w, const float* __restrict__ pp_b,
    const float* __restrict__ p1_g, const float* __restrict__ p1_b,
    const float* __restrict__ p1_w, const float* __restrict__ p1_bias,
    const float* __restrict__ p2_g, const float* __restrict__ p2_b,
    const float* __restrict__ p2_w, const float* __restrict__ p2_bias,
    const float* __restrict__ p3_g, const float* __restrict__ p3_b,
    const float* __restrict__ p3_w, const float* __restrict__ p3_bias) {
    int t = blockIdx.x * blockDim.x + threadIdx.x;
    if (t >= POS_TAB) return;
    float bh = (float)(t / 15 - 7), bw = (float)(t % 15 - 7);
    float p[POS_DIM], q[POS_DIM];
#pragma unroll
    for (int j = 0; j < POS_DIM; j++) p[j] = bh * pp_w[j] + bw * pp_w[POS_DIM + j] + pp_b[j];
    ln_relu12(p, q, p1_g, p1_b);
#pragma unroll
    for (int j = 0; j < POS_DIM; j++) {
        float s = p1_bias[j];
#pragma unroll
        for (int i = 0; i < POS_DIM; i++) s += q[i] * p1_w[i * POS_DIM + j];
        p[j] = s;
    }
    ln_relu12(p, q, p2_g, p2_b);
#pragma unroll
    for (int j = 0; j < POS_DIM; j++) {
        float s = p2_bias[j];
#pragma unroll
        for (int i = 0; i < POS_DIM; i++) s += q[i] * p2_w[i * POS_DIM + j];
        p[j] = s;
    }
    ln_relu12(p, q, p3_g, p3_b);
#pragma unroll
    for (int h = 0; h < HEADS; h++) {
        float s = p3_bias[h];
#pragma unroll
        for (int i = 0; i < POS_DIM; i++) s += q[i] * p3_w[i * HEADS + h];
        g_pos[t * HEADS + h] = s;
    }
}

// ---------------------------------------------------------------------------
// LayerNorm (C=192), warp per row, fp32 in -> bf16 out.
// mode 0: shift+window gather; mode 1: identity
// ---------------------------------------------------------------------------
__global__ void __launch_bounds__(256) ln_kernel(
    const float* __restrict__ in, __nv_bfloat16* __restrict__ out,
    const float* __restrict__ gamma, const float* __restrict__ beta, int mode) {
    int warp = threadIdx.x >> 5, lane = threadIdx.x & 31;
    int row = blockIdx.x * 8 + warp;
    size_t src;
    if (mode == 0) {
        int bb = row >> 14, rem = row & 16383;
        int win = rem >> 6, r = rem & 63;
        int wy = win >> 4, wx = win & 15, ry = r >> 3, rx = r & 7;
        int hh = (wy * WS + ry + SHIFT) & 127;
        int ww = (wx * WS + rx + SHIFT) & 127;
        src = (size_t)bb * LL + hh * WW_ + ww;
    } else src = (size_t)row;

    const float* p = in + src * CC;
    float v[6], s = 0.f, s2 = 0.f;
#pragma unroll
    for (int k = 0; k < 6; k++) { v[k] = p[lane + 32 * k]; s += v[k]; s2 += v[k] * v[k]; }
#pragma unroll
    for (int o = 16; o > 0; o >>= 1) {
        s += __shfl_xor_sync(0xFFFFFFFFu, s, o);
        s2 += __shfl_xor_sync(0xFFFFFFFFu, s2, o);
    }
    float mu = s * (1.0f / 192.0f);
    float rs = rsqrtf(s2 * (1.0f / 192.0f) - mu * mu + 1e-5f);
    __nv_bfloat16* q = out + (size_t)row * CC;
#pragma unroll
    for (int k = 0; k < 6; k++) {
        int c = lane + 32 * k;
        q[c] = __float2bfloat16((v[k] - mu) * rs * gamma[c] + beta[c]);
    }
}

// ---------------------------------------------------------------------------
// bf16 mma.sync GEMM: out[M,NOUT], 128x64 block tile, BK=32, cp.async x2 buf.
// A[M,K] bf16 row-major, BT[N,K] bf16 row-major. 8 warps (4x2), warp 32x32.
// EPI 0: +bias -> bf16   1: gelu(+bias) -> bf16
// EPI 2: +bias, window-reverse scatter, +res -> fp32   3: +bias +res -> fp32
// ---------------------------------------------------------------------------
#define AST 40                      // bf16 row stride (32 + 8 pad) -> 80B
#define ABUF_H ((128 + 64) * AST)   // bf16 elems per buffer

template <int EPI>
__global__ void __launch_bounds__(256) gemm_mma(
    const __nv_bfloat16* __restrict__ A, const __nv_bfloat16* __restrict__ BT,
    const float* __restrict__ bias, const float* __restrict__ res,
    void* __restrict__ outv, int K, int NOUT) {
    __shared__ __nv_bfloat16 smh[2 * ABUF_H];
    uint32_t sbase = smem_u32(smh);
    int tid = threadIdx.x;
    int wid = tid >> 5, lane = tid & 31;
    int wm = wid & 3, wn = wid >> 2;
    int m0 = blockIdx.y * 128, n0 = blockIdx.x * 64;
    const __nv_bfloat16* Ab = A + (size_t)m0 * K;
    const __nv_bfloat16* Bb = BT + (size_t)n0 * K;
    int NCH = K >> 5;

    float acc[2][4][4];
#pragma unroll
    for (int i = 0; i < 2; i++)
#pragma unroll
        for (int j = 0; j < 4; j++)
#pragma unroll
            for (int k = 0; k < 4; k++) acc[i][j][k] = 0.f;

    int la_row = tid >> 2, la_seg = tid & 3;  // 64 rows x 4 segs per pass

    // prologue: chunk 0
    {
        uint32_t dst = sbase;
#pragma unroll
        for (int i = 0; i < 2; i++) {
            int row = la_row + i * 64;
            cpasync16(dst + (row * AST + la_seg * 8) * 2, Ab + (size_t)row * K + la_seg * 8);
        }
        cpasync16(dst + ((128 + la_row) * AST + la_seg * 8) * 2, Bb + (size_t)la_row * K + la_seg * 8);
        cp_commit();
    }

    for (int c = 0; c < NCH; c++) {
        if (c + 1 < NCH) {
            int k0 = (c + 1) << 5;
            uint32_t dst = sbase + ((c + 1) & 1) * ABUF_H * 2;
#pragma unroll
            for (int i = 0; i < 2; i++) {
                int row = la_row + i * 64;
                cpasync16(dst + (row * AST + la_seg * 8) * 2, Ab + (size_t)row * K + k0 + la_seg * 8);
            }
            cpasync16(dst + ((128 + la_row) * AST + la_seg * 8) * 2,
                      Bb + (size_t)la_row * K + k0 + la_seg * 8);
        }
        cp_commit();
        cp_wait1();
        __syncthreads();

        const __nv_bfloat16* As = smh + (c & 1) * ABUF_H;
        const __nv_bfloat16* Bs = As + 128 * AST;
        const __nv_bfloat16* ap0 = As + (wm * 32 + (lane >> 2)) * AST + (lane & 3) * 2;
        const __nv_bfloat16* bp0 = Bs + (wn * 32 + (lane >> 2)) * AST + (lane & 3) * 2;

#pragma unroll
        for (int ks = 0; ks < 2; ks++) {
            int kb = ks * 16;
            uint32_t a[2][4], b[4][2];
#pragma unroll
            for (int mt = 0; mt < 2; mt++) {
                const __nv_bfloat16* ap = ap0 + mt * 16 * AST + kb;
                a[mt][0] = *(const uint32_t*)(ap);
                a[mt][1] = *(const uint32_t*)(ap + 8 * AST);
                a[mt][2] = *(const uint32_t*)(ap + 8);
                a[mt][3] = *(const uint32_t*)(ap + 8 * AST + 8);
            }
#pragma unroll
            for (int nt = 0; nt < 4; nt++) {
                const __nv_bfloat16* bp = bp0 + nt * 8 * AST + kb;
                b[nt][0] = *(const uint32_t*)(bp);
                b[nt][1] = *(const uint32_t*)(bp + 8);
            }
#pragma unroll
            for (int mt = 0; mt < 2; mt++)
#pragma unroll
                for (int nt = 0; nt < 4; nt++)
                    mma_bf16(acc[mt][nt], a[mt], b[nt]);
        }
        __syncthreads();
    }

    // epilogue
#pragma unroll
    for (int mt = 0; mt < 2; mt++) {
        int g0 = m0 + wm * 32 + mt * 16 + (lane >> 2);
        int g1 = g0 + 8;
        size_t ob0, ob1;
        if (EPI == 2) {
#pragma unroll
            for (int half = 0; half < 2; half++) {
                int g = half ? g1 : g0;
                int bb = g >> 14, rem = g & 16383;
                int win = rem >> 6, rr = rem & 63;
                int wy = win >> 4, wx = win & 15, ry = rr >> 3, rx = rr & 7;
                int hh = (wy * WS + ry + SHIFT) & 127;
                int ww = (wx * WS + rx + SHIFT) & 127;
                size_t ob = ((size_t)bb * LL + hh * WW_ + ww) * CC;
                if (half) ob1 = ob; else ob0 = ob;
            }
        } else {
            ob0 = (size_t)g0 * NOUT;
            ob1 = (size_t)g1 * NOUT;
        }
#pragma unroll
        for (int nt = 0; nt < 4; nt++) {
            int col = n0 + wn * 32 + nt * 8 + 2 * (lane & 3);
            float b0 = bias[col], b1 = bias[col + 1];
            float2 v0 = make_float2(acc[mt][nt][0] + b0, acc[mt][nt][1] + b1);
            float2 v1 = make_float2(acc[mt][nt][2] + b0, acc[mt][nt][3] + b1);
            if (EPI == 1) {
                v0.x = gelu_exact(v0.x); v0.y = gelu_exact(v0.y);
                v1.x = gelu_exact(v1.x); v1.y = gelu_exact(v1.y);
            }
            if (EPI == 0 || EPI == 1) {
                __nv_bfloat16* out = (__nv_bfloat16*)outv;
                *(__nv_bfloat162*)(out + ob0 + col) = __float22bfloat162_rn(v0);
                *(__nv_bfloat162*)(out + ob1 + col) = __float22bfloat162_rn(v1);
            } else {
                float* out = (float*)outv;
                float2 r0 = *(const float2*)(res + ob0 + col);
                float2 r1 = *(const float2*)(res + ob1 + col);
                v0.x += r0.x; v0.y += r0.y;
                v1.x += r1.x; v1.y += r1.y;
                *(float2*)(out + ob0 + col) = v0;
                *(float2*)(out + ob1 + col) = v1;
            }
        }
    }
}

// ---------------------------------------------------------------------------
// Windowed attention: bf16 K/V in smem (48KB), fp32 online softmax.
// 384 threads = (head, query-row). Output bf16.
// ---------------------------------------------------------------------------
__global__ void __launch_bounds__(384) attn_kernel(
    const __nv_bfloat16* __restrict__ qkv, const float* __restrict__ pos,
    __nv_bfloat16* __restrict__ outp) {
    extern __shared__ __nv_bfloat16 smh[];
    __nv_bfloat16* k_s = smh;                  // [64][192]
    __nv_bfloat16* v_s = smh + NWIN * CC;

    int w = blockIdx.x;
    int tid = threadIdx.x;
    const __nv_bfloat16* base = qkv + (size_t)w * NWIN * (3 * CC);

    uint4* k4 = (uint4*)k_s;
    uint4* v4 = (uint4*)v_s;
    for (int idx = tid; idx < NWIN * 24; idx += 384) {
        int j = idx / 24, c = idx % 24;
        k4[j * 24 + c] = *(const uint4*)(base + (size_t)j * 576 + 192 + c * 8);
        v4[j * 24 + c] = *(const uint4*)(base + (size_t)j * 576 + 384 + c * 8);
    }
    __syncthreads();

    int h = tid / NWIN;
    int r = tid % NWIN;
    int ry = r >> 3, rx = r & 7;
    int winloc = w & 255;
    int wy = winloc >> 4, wx = winloc & 15;
    int lh_r = (wy == 15) ? (ry < (WS - SHIFT) ? 1 : 2) : 0;
    int lw_r = (wx == 15) ? (rx < (WS - SHIFT) ? 1 : 2) : 0;

    // load q (32 bf16), scale, keep as float2[16]
    float2 q2[16];
    {
        const uint4* qp = (const uint4*)(base + (size_t)r * 576 + h * HD);
#pragma unroll
        for (int c = 0; c < 4; c++) {
            uint4 u = qp[c];
            const __nv_bfloat162* pb = (const __nv_bfloat162*)&u;
#pragma unroll
            for (int t = 0; t < 4; t++) {
                float2 f = __bfloat1622float2(pb[t]);
                q2[c * 4 + t] = make_float2(f.x * 0.17677669529663687f,
                                            f.y * 0.17677669529663687f);
            }
        }
    }

    const float* pb_ = pos + (((ry + 7) * 15) + (rx + 7)) * HEADS + h;
    const uint4* ks4 = (const uint4*)(k_s + h * HD);
    const uint4* vs4 = (const uint4*)(v_s + h * HD);
    const int rstride4 = CC / 8;  // uint4 per row = 24

    float mx = -1e30f, sum = 0.f;
    float2 a2[16];
#pragma unroll
    for (int d = 0; d < 16; d++) a2[d] = make_float2(0.f, 0.f);

    for (int jy = 0; jy < 8; jy++) {
        int lh_j = (wy == 15) ? (jy < (WS - SHIFT) ? 1 : 2) : 0;
        bool hbad = (lh_j != lh_r);
        const float* pby = pb_ - jy * 90;
#pragma unroll
        for (int jx = 0; jx < 8; jx++) {
            int j = jy * 8 + jx;
            const uint4* kj = ks4 + j * rstride4;
            float s0 = 0.f, s1 = 0.f;
#pragma unroll
            for (int c = 0; c < 4; c++) {
                uint4 u = kj[c];
                const __nv_bfloat162* pk = (const __nv_bfloat162*)&u;
#pragma unroll
                for (int t = 0; t < 4; t++) {
                    float2 f = __bfloat1622float2(pk[t]);
                    s0 += q2[c * 4 + t].x * f.x;
                    s1 += q2[c * 4 + t].y * f.y;
                }
            }
            float s = s0 + s1;
            s += pby[-(jx * 6)];
            int lw_j = (wx == 15) ? (jx < (WS - SHIFT) ? 1 : 2) : 0;
            if (hbad || (lw_j != lw_r)) s -= 100.0f;

            float p;
            if (s > mx) {
                float cr = __expf(mx - s);
                mx = s;
                sum *= cr;
#pragma unroll
                for (int d = 0; d < 16; d++) { a2[d].x *= cr; a2[d].y *= cr; }
                p = 1.0f;
            } else {
                p = __expf(s - mx);
            }
            sum += p;
            const uint4* vj = vs4 + j * rstride4;
#pragma unroll
            for (int c = 0; c < 4; c++) {
                uint4 u = vj[c];
                const __nv_bfloat162* pv = (const __nv_bfloat162*)&u;
#pragma unroll
                for (int t = 0; t < 4; t++) {
                    float2 f = __bfloat1622float2(pv[t]);
                    a2[c * 4 + t].x += p * f.x;
                    a2[c * 4 + t].y += p * f.y;
                }
            }
        }
    }

    float inv = 1.0f / sum;
    __nv_bfloat162* op = (__nv_bfloat162*)(outp + (size_t)(w * NWIN + r) * CC + h * HD);
#pragma unroll
    for (int d = 0; d < 16; d++) {
        op[d] = __float22bfloat162_rn(make_float2(a2[d].x * inv, a2[d].y * inv));
    }
}

// ---------------------------------------------------------------------------
// Launch
// ---------------------------------------------------------------------------
extern "C" void kernel_launch(void* const* d_in, const int* in_sizes, int n_in,
                              void* d_out, int out_size) {
    const float* x      = (const float*)d_in[0];
    const float* n1_g   = (const float*)d_in[4];
    const float* n1_b   = (const float*)d_in[5];
    const float* qkv_w  = (const float*)d_in[6];
    const float* qkv_b  = (const float*)d_in[7];
    const float* proj_w = (const float*)d_in[8];
    const float* proj_b = (const float*)d_in[9];
    const float* pp_w   = (const float*)d_in[10];
    const float* pp_b   = (const float*)d_in[11];
    const float* p1_g   = (const float*)d_in[12];
    const float* p1_b   = (const float*)d_in[13];
    const float* p1_w   = (const float*)d_in[14];
    const float* p1_bi  = (const float*)d_in[15];
    const float* p2_g   = (const float*)d_in[16];
    const float* p2_b   = (const float*)d_in[17];
    const float* p2_w   = (const float*)d_in[18];
    const float* p2_bi  = (const float*)d_in[19];
    const float* p3_g   = (const float*)d_in[20];
    const float* p3_b   = (const float*)d_in[21];
    const float* p3_w   = (const float*)d_in[22];
    const float* p3_bi  = (const float*)d_in[23];
    const float* n2_g   = (const float*)d_in[24];
    const float* n2_b   = (const float*)d_in[25];
    const float* fc1_w  = (const float*)d_in[26];
    const float* fc1_b  = (const float*)d_in[27];
    const float* fc2_w  = (const float*)d_in[28];
    const float* fc2_b  = (const float*)d_in[29];
    float* out = (float*)d_out;

    __nv_bfloat16 *xw, *qkv, *attn, *ln2, *hid;
    __nv_bfloat16 *wt_qkv, *wt_proj, *wt_fc1, *wt_fc2;
    float* pos;
    cudaGetSymbolAddress((void**)&xw,   gb_xw);
    cudaGetSymbolAddress((void**)&qkv,  gb_qkv);
    cudaGetSymbolAddress((void**)&attn, gb_attn);
    cudaGetSymbolAddress((void**)&ln2,  gb_ln2);
    cudaGetSymbolAddress((void**)&hid,  gb_hid);
    cudaGetSymbolAddress((void**)&pos,  g_pos);
    cudaGetSymbolAddress((void**)&wt_qkv,  gb_wt_qkv);
    cudaGetSymbolAddress((void**)&wt_proj, gb_wt_proj);
    cudaGetSymbolAddress((void**)&wt_fc1,  gb_wt_fc1);
    cudaGetSymbolAddress((void**)&wt_fc2,  gb_wt_fc2);

    static bool attr_set = false;
    if (!attr_set) {
        cudaFuncSetAttribute(attn_kernel, cudaFuncAttributeMaxDynamicSharedMemorySize,
                             2 * NWIN * CC * (int)sizeof(__nv_bfloat16));
        attr_set = true;
    }

    // 0. weight transposes (bf16)
    transpose_w<<<(3 * CC * CC + 255) / 256, 256>>>(qkv_w, wt_qkv, CC, 3 * CC);
    transpose_w<<<(CC * CC + 255) / 256, 256>>>(proj_w, wt_proj, CC, CC);
    transpose_w<<<(CC * HIDDEN + 255) / 256, 256>>>(fc1_w, wt_fc1, CC, HIDDEN);
    transpose_w<<<(HIDDEN * CC + 255) / 256, 256>>>(fc2_w, wt_fc2, HIDDEN, CC);

    // 1. position-bias MLP
    pos_mlp_kernel<<<1, 256>>>(pp_w, pp_b, p1_g, p1_b, p1_w, p1_bi,
                               p2_g, p2_b, p2_w, p2_bi, p3_g, p3_b, p3_w, p3_bi);

    // 2. LN1 + shift + window partition -> bf16
    ln_kernel<<<MROWS / 8, 256>>>(x, xw, n1_g, n1_b, 0);

    // 3. QKV GEMM -> bf16
    gemm_mma<0><<<dim3(576 / 64, MROWS / 128), 256>>>(xw, wt_qkv, qkv_b, nullptr, qkv, CC, 576);

    // 4. attention -> bf16
    attn_kernel<<<NWINDOWS, 384, 2 * NWIN * CC * (int)sizeof(__nv_bfloat16)>>>(qkv, pos, attn);

    // 5. proj + window-reverse + residual -> fp32 y
    gemm_mma<2><<<dim3(CC / 64, MROWS / 128), 256>>>(attn, wt_proj, proj_b, x, out, CC, CC);

    // 6. LN2 -> bf16
    ln_kernel<<<MROWS / 8, 256>>>(out, ln2, n2_g, n2_b, 1);

    // 7. FC1 + GELU -> bf16
    gemm_mma<1><<<dim3(HIDDEN / 64, MROWS / 128), 256>>>(ln2, wt_fc1, fc1_b, nullptr, hid, CC, HIDDEN);

    // 8. FC2 + residual -> fp32 out
    gemm_mma<3><<<dim3(CC / 64, MROWS / 128), 256>>>(hid, wt_fc2, fc2_b, out, out, HIDDEN, CC);
}

// round 5
// speedup vs baseline: 3.3099x; 1.0185x over previous
#include <cuda_runtime.h>
#include <cuda_bf16.h>
#include <math.h>
#include <stdint.h>

// ---------------------------------------------------------------------------
// Problem constants
// ---------------------------------------------------------------------------
#define BATCH   8
#define HH      128
#define WW_     128
#define LL      (HH*WW_)
#define CC      192
#define HEADS   6
#define HD      32
#define WS      8
#define NWIN    64
#define SHIFT   4
#define HIDDEN  768
#define MROWS   (BATCH*LL)                 // 131072
#define NWINDOWS (BATCH*(HH/WS)*(WW_/WS))  // 2048
#define POS_DIM 12
#define POS_TAB 225

// ---------------------------------------------------------------------------
// Device scratch (bf16 activations, fp32 residual stream)
// ---------------------------------------------------------------------------
__device__ __nv_bfloat16 gb_xw[(size_t)MROWS * CC];
__device__ __nv_bfloat16 gb_qkv[(size_t)MROWS * 3 * CC];
__device__ __nv_bfloat16 gb_attn[(size_t)MROWS * CC];
__device__ __nv_bfloat16 gb_ln2[(size_t)MROWS * CC];
__device__ __nv_bfloat16 gb_hid[(size_t)MROWS * HIDDEN];
__device__ float g_pos[POS_TAB * HEADS];
__device__ __nv_bfloat16 gb_wt_qkv[3 * CC * CC];
__device__ __nv_bfloat16 gb_wt_proj[CC * CC];
__device__ __nv_bfloat16 gb_wt_fc1[HIDDEN * CC];
__device__ __nv_bfloat16 gb_wt_fc2[CC * HIDDEN];

// ---------------------------------------------------------------------------
// Helpers
// ---------------------------------------------------------------------------
__device__ __forceinline__ uint32_t smem_u32(const void* p) {
    uint32_t a;
    asm("{ .reg .u64 t; cvta.to.shared.u64 t, %1; cvt.u32.u64 %0, t; }" : "=r"(a) : "l"(p));
    return a;
}
__device__ __forceinline__ void cpasync16(uint32_t s, const void* g) {
    asm volatile("cp.async.cg.shared.global [%0], [%1], 16;" :: "r"(s), "l"(g));
}
__device__ __forceinline__ void cp_commit() {
    asm volatile("cp.async.commit_group;" ::: "memory");
}
__device__ __forceinline__ void cp_wait1() {
    asm volatile("cp.async.wait_group 1;" ::: "memory");
}
__device__ __forceinline__ void ldsm_x4(uint32_t addr, uint32_t* r) {
    asm volatile("ldmatrix.sync.aligned.m8n8.x4.shared.b16 {%0,%1,%2,%3}, [%4];"
                 : "=r"(r[0]), "=r"(r[1]), "=r"(r[2]), "=r"(r[3]) : "r"(addr));
}
__device__ __forceinline__ void mma_bf16(float* d, const uint32_t* a, const uint32_t* b) {
    asm volatile(
        "mma.sync.aligned.m16n8k16.row.col.f32.bf16.bf16.f32 "
        "{%0,%1,%2,%3}, {%4,%5,%6,%7}, {%8,%9}, {%0,%1,%2,%3};"
        : "+f"(d[0]), "+f"(d[1]), "+f"(d[2]), "+f"(d[3])
        : "r"(a[0]), "r"(a[1]), "r"(a[2]), "r"(a[3]), "r"(b[0]), "r"(b[1]));
}
__device__ __forceinline__ float gelu_exact(float x) {
    return 0.5f * x * (1.0f + erff(x * 0.7071067811865476f));
}

// ---------------------------------------------------------------------------
// Weight transpose (W[K,N] -> WT[N,K]) with bf16 rounding
// ---------------------------------------------------------------------------
__global__ void transpose_w(const float* __restrict__ w, __nv_bfloat16* __restrict__ wt,
                            int K, int N) {
    int i = blockIdx.x * 256 + threadIdx.x;
    if (i >= K * N) return;
    int k = i / N, n = i % N;
    wt[(size_t)n * K + k] = __float2bfloat16(w[i]);
}

// ---------------------------------------------------------------------------
// Position-bias MLP
// ---------------------------------------------------------------------------
__device__ __forceinline__ void ln_relu12(const float* p, float* q,
                                          const float* g, const float* b) {
    float s = 0.f, s2 = 0.f;
#pragma unroll
    for (int i = 0; i < POS_DIM; i++) { s += p[i]; s2 += p[i] * p[i]; }
    float mu = s / 12.0f;
    float var = s2 / 12.0f - mu * mu;
    float rs = rsqrtf(var + 1e-5f);
#pragma unroll
    for (int i = 0; i < POS_DIM; i++) q[i] = fmaxf((p[i] - mu) * rs * g[i] + b[i], 0.0f);
}

__global__ void pos_mlp_kernel(
    const float* __restrict__ pp_w, const float* __restrict__ pp_b,
    const float* __restrict__ p1_g, const float* __restrict__ p1_b,
    const float* __restrict__ p1_w, const float* __restrict__ p1_bias,
    const float* __restrict__ p2_g, const float* __restrict__ p2_b,
    const float* __restrict__ p2_w, const float* __restrict__ p2_bias,
    const float* __restrict__ p3_g, const float* __restrict__ p3_b,
    const float* __restrict__ p3_w, const float* __restrict__ p3_bias) {
    int t = blockIdx.x * blockDim.x + threadIdx.x;
    if (t >= POS_TAB) return;
    float bh = (float)(t / 15 - 7), bw = (float)(t % 15 - 7);
    float p[POS_DIM], q[POS_DIM];
#pragma unroll
    for (int j = 0; j < POS_DIM; j++) p[j] = bh * pp_w[j] + bw * pp_w[POS_DIM + j] + pp_b[j];
    ln_relu12(p, q, p1_g, p1_b);
#pragma unroll
    for (int j = 0; j < POS_DIM; j++) {
        float s = p1_bias[j];
#pragma unroll
        for (int i = 0; i < POS_DIM; i++) s += q[i] * p1_w[i * POS_DIM + j];
        p[j] = s;
    }
    ln_relu12(p, q, p2_g, p2_b);
#pragma unroll
    for (int j = 0; j < POS_DIM; j++) {
        float s = p2_bias[j];
#pragma unroll
        for (int i = 0; i < POS_DIM; i++) s += q[i] * p2_w[i * POS_DIM + j];
        p[j] = s;
    }
    ln_relu12(p, q, p3_g, p3_b);
#pragma unroll
    for (int h = 0; h < HEADS; h++) {
        float s = p3_bias[h];
#pragma unroll
        for (int i = 0; i < POS_DIM; i++) s += q[i] * p3_w[i * HEADS + h];
        g_pos[t * HEADS + h] = s;
    }
}

// ---------------------------------------------------------------------------
// LayerNorm (C=192), warp per row, fp32 in -> bf16 out.
// ---------------------------------------------------------------------------
__global__ void __launch_bounds__(256) ln_kernel(
    const float* __restrict__ in, __nv_bfloat16* __restrict__ out,
    const float* __restrict__ gamma, const float* __restrict__ beta, int mode) {
    int warp = threadIdx.x >> 5, lane = threadIdx.x & 31;
    int row = blockIdx.x * 8 + warp;
    size_t src;
    if (mode == 0) {
        int bb = row >> 14, rem = row & 16383;
        int win = rem >> 6, r = rem & 63;
        int wy = win >> 4, wx = win & 15, ry = r >> 3, rx = r & 7;
        int hh = (wy * WS + ry + SHIFT) & 127;
        int ww = (wx * WS + rx + SHIFT) & 127;
        src = (size_t)bb * LL + hh * WW_ + ww;
    } else src = (size_t)row;

    const float* p = in + src * CC;
    float v[6], s = 0.f, s2 = 0.f;
#pragma unroll
    for (int k = 0; k < 6; k++) { v[k] = p[lane + 32 * k]; s += v[k]; s2 += v[k] * v[k]; }
#pragma unroll
    for (int o = 16; o > 0; o >>= 1) {
        s += __shfl_xor_sync(0xFFFFFFFFu, s, o);
        s2 += __shfl_xor_sync(0xFFFFFFFFu, s2, o);
    }
    float mu = s * (1.0f / 192.0f);
    float rs = rsqrtf(s2 * (1.0f / 192.0f) - mu * mu + 1e-5f);
    __nv_bfloat16* q = out + (size_t)row * CC;
#pragma unroll
    for (int k = 0; k < 6; k++) {
        int c = lane + 32 * k;
        q[c] = __float2bfloat16((v[k] - mu) * rs * gamma[c] + beta[c]);
    }
}

// ---------------------------------------------------------------------------
// bf16 mma GEMM v2: 128x64 tile, BK=64, ldmatrix fragments, XOR-swizzled smem.
// SMEM layout: 16B chunks; row r (0..191: 0-127 A, 128-191 B), 8 chunks/row;
// chunk c of row r stored at index r*8 + (c ^ (r&7)).
// 8 warps: wm = wid&3 (32 rows), wn = wid>>2 (32 cols).
// EPI 0: +bias -> bf16   1: gelu(+bias) -> bf16
// EPI 2: +bias, window-reverse scatter, +res -> fp32   3: +bias +res -> fp32
// ---------------------------------------------------------------------------
#define CH_PER_BUF (192 * 8)   // 16B chunks per buffer

template <int EPI>
__global__ void __launch_bounds__(256) gemm_mma(
    const __nv_bfloat16* __restrict__ A, const __nv_bfloat16* __restrict__ BT,
    const float* __restrict__ bias, const float* __restrict__ res,
    void* __restrict__ outv, int K, int NOUT) {
    __shared__ __align__(16) uint4 smq[2 * CH_PER_BUF];
    uint32_t sbase = smem_u32(smq);
    int tid = threadIdx.x;
    int wid = tid >> 5, lane = tid & 31;
    int wm = wid & 3, wn = wid >> 2;
    int m0 = blockIdx.y * 128, n0 = blockIdx.x * 64;
    const __nv_bfloat16* Ab = A + (size_t)m0 * K;
    const __nv_bfloat16* Bb = BT + (size_t)n0 * K;
    int NCH = K >> 6;

    float acc[2][4][4];
#pragma unroll
    for (int i = 0; i < 2; i++)
#pragma unroll
        for (int j = 0; j < 4; j++)
#pragma unroll
            for (int k = 0; k < 4; k++) acc[i][j][k] = 0.f;

    // cp.async indices
    int a_row = tid >> 1;                 // 0..127
    int a_ch0 = (tid & 1) * 4;            // chunks 0-3 or 4-7
    int b_row = tid >> 2;                 // 0..63
    int b_ch0 = (tid & 3) * 2;            // 2 chunks

    // ldmatrix lane addressing
    int l15 = lane & 15, lhi = lane >> 4;
    int a_lrow = wm * 32 + l15;                              // + mt*16
    int a_sw = l15 & 7;
    int b_lrow = 128 + wn * 32 + (lhi << 3) + (lane & 7);    // + nt16*16
    int b_sw = lane & 7;
    int b_chlo = (lane >> 3) & 1;

    // prologue: chunk 0
    {
        uint32_t dst = sbase;
#pragma unroll
        for (int i = 0; i < 4; i++) {
            int ch = a_ch0 + i;
            cpasync16(dst + (a_row * 8 + (ch ^ (a_row & 7))) * 16,
                      Ab + (size_t)a_row * K + ch * 8);
        }
#pragma unroll
        for (int i = 0; i < 2; i++) {
            int ch = b_ch0 + i;
            cpasync16(dst + ((128 + b_row) * 8 + (ch ^ (b_row & 7))) * 16,
                      Bb + (size_t)b_row * K + ch * 8);
        }
        cp_commit();
    }

    for (int c = 0; c < NCH; c++) {
        if (c + 1 < NCH) {
            int k0 = (c + 1) << 6;
            uint32_t dst = sbase + ((c + 1) & 1) * CH_PER_BUF * 16;
#pragma unroll
            for (int i = 0; i < 4; i++) {
                int ch = a_ch0 + i;
                cpasync16(dst + (a_row * 8 + (ch ^ (a_row & 7))) * 16,
                          Ab + (size_t)a_row * K + k0 + ch * 8);
            }
#pragma unroll
            for (int i = 0; i < 2; i++) {
                int ch = b_ch0 + i;
                cpasync16(dst + ((128 + b_row) * 8 + (ch ^ (b_row & 7))) * 16,
                          Bb + (size_t)b_row * K + k0 + ch * 8);
            }
        }
        cp_commit();
        cp_wait1();
        __syncthreads();

        uint32_t buf = sbase + (c & 1) * CH_PER_BUF * 16;
#pragma unroll
        for (int ks = 0; ks < 4; ks++) {
            uint32_t a[2][4], b[2][4];
            int achk = 2 * ks + lhi;
#pragma unroll
            for (int mt = 0; mt < 2; mt++) {
                uint32_t idx = (a_lrow + mt * 16) * 8 + (achk ^ a_sw);
                ldsm_x4(buf + idx * 16, a[mt]);
            }
            int bchk = 2 * ks + b_chlo;
#pragma unroll
            for (int nt16 = 0; nt16 < 2; nt16++) {
                uint32_t idx = (b_lrow + nt16 * 16) * 8 + (bchk ^ b_sw);
                ldsm_x4(buf + idx * 16, b[nt16]);
            }
#pragma unroll
            for (int mt = 0; mt < 2; mt++) {
#pragma unroll
                for (int nt16 = 0; nt16 < 2; nt16++) {
                    mma_bf16(acc[mt][nt16 * 2 + 0], a[mt], &b[nt16][0]);
                    mma_bf16(acc[mt][nt16 * 2 + 1], a[mt], &b[nt16][2]);
                }
            }
        }
        __syncthreads();
    }

    // epilogue
#pragma unroll
    for (int mt = 0; mt < 2; mt++) {
        int g0 = m0 + wm * 32 + mt * 16 + (lane >> 2);
        int g1 = g0 + 8;
        size_t ob0, ob1;
        if (EPI == 2) {
#pragma unroll
            for (int half = 0; half < 2; half++) {
                int g = half ? g1 : g0;
                int bb = g >> 14, rem = g & 16383;
                int win = rem >> 6, rr = rem & 63;
                int wy = win >> 4, wx = win & 15, ry = rr >> 3, rx = rr & 7;
                int hh = (wy * WS + ry + SHIFT) & 127;
                int ww = (wx * WS + rx + SHIFT) & 127;
                size_t ob = ((size_t)bb * LL + hh * WW_ + ww) * CC;
                if (half) ob1 = ob; else ob0 = ob;
            }
        } else {
            ob0 = (size_t)g0 * NOUT;
            ob1 = (size_t)g1 * NOUT;
        }
#pragma unroll
        for (int nt = 0; nt < 4; nt++) {
            int col = n0 + wn * 32 + nt * 8 + 2 * (lane & 3);
            float b0 = bias[col], b1 = bias[col + 1];
            float2 v0 = make_float2(acc[mt][nt][0] + b0, acc[mt][nt][1] + b1);
            float2 v1 = make_float2(acc[mt][nt][2] + b0, acc[mt][nt][3] + b1);
            if (EPI == 1) {
                v0.x = gelu_exact(v0.x); v0.y = gelu_exact(v0.y);
                v1.x = gelu_exact(v1.x); v1.y = gelu_exact(v1.y);
            }
            if (EPI == 0 || EPI == 1) {
                __nv_bfloat16* out = (__nv_bfloat16*)outv;
                *(__nv_bfloat162*)(out + ob0 + col) = __float22bfloat162_rn(v0);
                *(__nv_bfloat162*)(out + ob1 + col) = __float22bfloat162_rn(v1);
            } else {
                float* out = (float*)outv;
                float2 r0 = *(const float2*)(res + ob0 + col);
                float2 r1 = *(const float2*)(res + ob1 + col);
                v0.x += r0.x; v0.y += r0.y;
                v1.x += r1.x; v1.y += r1.y;
                *(float2*)(out + ob0 + col) = v0;
                *(float2*)(out + ob1 + col) = v1;
            }
        }
    }
}

// ---------------------------------------------------------------------------
// Windowed attention: bf16 K/V in smem (48KB), fp32 online softmax.
// ---------------------------------------------------------------------------
__global__ void __launch_bounds__(384) attn_kernel(
    const __nv_bfloat16* __restrict__ qkv, const float* __restrict__ pos,
    __nv_bfloat16* __restrict__ outp) {
    extern __shared__ __nv_bfloat16 smh[];
    __nv_bfloat16* k_s = smh;
    __nv_bfloat16* v_s = smh + NWIN * CC;

    int w = blockIdx.x;
    int tid = threadIdx.x;
    const __nv_bfloat16* base = qkv + (size_t)w * NWIN * (3 * CC);

    uint4* k4 = (uint4*)k_s;
    uint4* v4 = (uint4*)v_s;
    for (int idx = tid; idx < NWIN * 24; idx += 384) {
        int j = idx / 24, c = idx % 24;
        k4[j * 24 + c] = *(const uint4*)(base + (size_t)j * 576 + 192 + c * 8);
        v4[j * 24 + c] = *(const uint4*)(base + (size_t)j * 576 + 384 + c * 8);
    }
    __syncthreads();

    int h = tid / NWIN;
    int r = tid % NWIN;
    int ry = r >> 3, rx = r & 7;
    int winloc = w & 255;
    int wy = winloc >> 4, wx = winloc & 15;
    int lh_r = (wy == 15) ? (ry < (WS - SHIFT) ? 1 : 2) : 0;
    int lw_r = (wx == 15) ? (rx < (WS - SHIFT) ? 1 : 2) : 0;

    float2 q2[16];
    {
        const uint4* qp = (const uint4*)(base + (size_t)r * 576 + h * HD);
#pragma unroll
        for (int c = 0; c < 4; c++) {
            uint4 u = qp[c];
            const __nv_bfloat162* pb = (const __nv_bfloat162*)&u;
#pragma unroll
            for (int t = 0; t < 4; t++) {
                float2 f = __bfloat1622float2(pb[t]);
                q2[c * 4 + t] = make_float2(f.x * 0.17677669529663687f,
                                            f.y * 0.17677669529663687f);
            }
        }
    }

    const float* pb_ = pos + (((ry + 7) * 15) + (rx + 7)) * HEADS + h;
    const uint4* ks4 = (const uint4*)(k_s + h * HD);
    const uint4* vs4 = (const uint4*)(v_s + h * HD);
    const int rstride4 = CC / 8;

    float mx = -1e30f, sum = 0.f;
    float2 a2[16];
#pragma unroll
    for (int d = 0; d < 16; d++) a2[d] = make_float2(0.f, 0.f);

    for (int jy = 0; jy < 8; jy++) {
        int lh_j = (wy == 15) ? (jy < (WS - SHIFT) ? 1 : 2) : 0;
        bool hbad = (lh_j != lh_r);
        const float* pby = pb_ - jy * 90;
#pragma unroll
        for (int jx = 0; jx < 8; jx++) {
            int j = jy * 8 + jx;
            const uint4* kj = ks4 + j * rstride4;
            float s0 = 0.f, s1 = 0.f;
#pragma unroll
            for (int c = 0; c < 4; c++) {
                uint4 u = kj[c];
                const __nv_bfloat162* pk = (const __nv_bfloat162*)&u;
#pragma unroll
                for (int t = 0; t < 4; t++) {
                    float2 f = __bfloat1622float2(pk[t]);
                    s0 += q2[c * 4 + t].x * f.x;
                    s1 += q2[c * 4 + t].y * f.y;
                }
            }
            float s = s0 + s1;
            s += pby[-(jx * 6)];
            int lw_j = (wx == 15) ? (jx < (WS - SHIFT) ? 1 : 2) : 0;
            if (hbad || (lw_j != lw_r)) s -= 100.0f;

            float p;
            if (s > mx) {
                float cr = __expf(mx - s);
                mx = s;
                sum *= cr;
#pragma unroll
                for (int d = 0; d < 16; d++) { a2[d].x *= cr; a2[d].y *= cr; }
                p = 1.0f;
            } else {
                p = __expf(s - mx);
            }
            sum += p;
            const uint4* vj = vs4 + j * rstride4;
#pragma unroll
            for (int c = 0; c < 4; c++) {
                uint4 u = vj[c];
                const __nv_bfloat162* pv = (const __nv_bfloat162*)&u;
#pragma unroll
                for (int t = 0; t < 4; t++) {
                    float2 f = __bfloat1622float2(pv[t]);
                    a2[c * 4 + t].x += p * f.x;
                    a2[c * 4 + t].y += p * f.y;
                }
            }
        }
    }

    float inv = 1.0f / sum;
    __nv_bfloat162* op = (__nv_bfloat162*)(outp + (size_t)(w * NWIN + r) * CC + h * HD);
#pragma unroll
    for (int d = 0; d < 16; d++) {
        op[d] = __float22bfloat162_rn(make_float2(a2[d].x * inv, a2[d].y * inv));
    }
}

// ---------------------------------------------------------------------------
// Launch
// ---------------------------------------------------------------------------
extern "C" void kernel_launch(void* const* d_in, const int* in_sizes, int n_in,
                              void* d_out, int out_size) {
    const float* x      = (const float*)d_in[0];
    const float* n1_g   = (const float*)d_in[4];
    const float* n1_b   = (const float*)d_in[5];
    const float* qkv_w  = (const float*)d_in[6];
    const float* qkv_b  = (const float*)d_in[7];
    const float* proj_w = (const float*)d_in[8];
    const float* proj_b = (const float*)d_in[9];
    const float* pp_w   = (const float*)d_in[10];
    const float* pp_b   = (const float*)d_in[11];
    const float* p1_g   = (const float*)d_in[12];
    const float* p1_b   = (const float*)d_in[13];
    const float* p1_w   = (const float*)d_in[14];
    const float* p1_bi  = (const float*)d_in[15];
    const float* p2_g   = (const float*)d_in[16];
    const float* p2_b   = (const float*)d_in[17];
    const float* p2_w   = (const float*)d_in[18];
    const float* p2_bi  = (const float*)d_in[19];
    const float* p3_g   = (const float*)d_in[20];
    const float* p3_b   = (const float*)d_in[21];
    const float* p3_w   = (const float*)d_in[22];
    const float* p3_bi  = (const float*)d_in[23];
    const float* n2_g   = (const float*)d_in[24];
    const float* n2_b   = (const float*)d_in[25];
    const float* fc1_w  = (const float*)d_in[26];
    const float* fc1_b  = (const float*)d_in[27];
    const float* fc2_w  = (const float*)d_in[28];
    const float* fc2_b  = (const float*)d_in[29];
    float* out = (float*)d_out;

    __nv_bfloat16 *xw, *qkv, *attn, *ln2, *hid;
    __nv_bfloat16 *wt_qkv, *wt_proj, *wt_fc1, *wt_fc2;
    float* pos;
    cudaGetSymbolAddress((void**)&xw,   gb_xw);
    cudaGetSymbolAddress((void**)&qkv,  gb_qkv);
    cudaGetSymbolAddress((void**)&attn, gb_attn);
    cudaGetSymbolAddress((void**)&ln2,  gb_ln2);
    cudaGetSymbolAddress((void**)&hid,  gb_hid);
    cudaGetSymbolAddress((void**)&pos,  g_pos);
    cudaGetSymbolAddress((void**)&wt_qkv,  gb_wt_qkv);
    cudaGetSymbolAddress((void**)&wt_proj, gb_wt_proj);
    cudaGetSymbolAddress((void**)&wt_fc1,  gb_wt_fc1);
    cudaGetSymbolAddress((void**)&wt_fc2,  gb_wt_fc2);

    static bool attr_set = false;
    if (!attr_set) {
        cudaFuncSetAttribute(attn_kernel, cudaFuncAttributeMaxDynamicSharedMemorySize,
                             2 * NWIN * CC * (int)sizeof(__nv_bfloat16));
        attr_set = true;
    }

    // 0. weight transposes (bf16)
    transpose_w<<<(3 * CC * CC + 255) / 256, 256>>>(qkv_w, wt_qkv, CC, 3 * CC);
    transpose_w<<<(CC * CC + 255) / 256, 256>>>(proj_w, wt_proj, CC, CC);
    transpose_w<<<(CC * HIDDEN + 255) / 256, 256>>>(fc1_w, wt_fc1, CC, HIDDEN);
    transpose_w<<<(HIDDEN * CC + 255) / 256, 256>>>(fc2_w, wt_fc2, HIDDEN, CC);

    // 1. position-bias MLP
    pos_mlp_kernel<<<1, 256>>>(pp_w, pp_b, p1_g, p1_b, p1_w, p1_bi,
                               p2_g, p2_b, p2_w, p2_bi, p3_g, p3_b, p3_w, p3_bi);

    // 2. LN1 + shift + window partition -> bf16
    ln_kernel<<<MROWS / 8, 256>>>(x, xw, n1_g, n1_b, 0);

    // 3. QKV GEMM -> bf16  (K=192 = 3 chunks of 64)
    gemm_mma<0><<<dim3(576 / 64, MROWS / 128), 256>>>(xw, wt_qkv, qkv_b, nullptr, qkv, CC, 576);

    // 4. attention -> bf16
    attn_kernel<<<NWINDOWS, 384, 2 * NWIN * CC * (int)sizeof(__nv_bfloat16)>>>(qkv, pos, attn);

    // 5. proj + window-reverse + residual -> fp32 y
    gemm_mma<2><<<dim3(CC / 64, MROWS / 128), 256>>>(attn, wt_proj, proj_b, x, out, CC, CC);

    // 6. LN2 -> bf16
    ln_kernel<<<MROWS / 8, 256>>>(out, ln2, n2_g, n2_b, 1);

    // 7. FC1 + GELU -> bf16
    gemm_mma<1><<<dim3(HIDDEN / 64, MROWS / 128), 256>>>(ln2, wt_fc1, fc1_b, nullptr, hid, CC, HIDDEN);

    // 8. FC2 + residual -> fp32 out
    gemm_mma<3><<<dim3(CC / 64, MROWS / 128), 256>>>(hid, wt_fc2, fc2_b, out, out, HIDDEN, CC);
}

// round 6
// speedup vs baseline: 3.6247x; 1.0951x over previous
#include <cuda_runtime.h>
#include <cuda_bf16.h>
#include <math.h>
#include <stdint.h>

// ---------------------------------------------------------------------------
// Problem constants
// ---------------------------------------------------------------------------
#define BATCH   8
#define HH      128
#define WW_     128
#define LL      (HH*WW_)
#define CC      192
#define HEADS   6
#define HD      32
#define WS      8
#define NWIN    64
#define SHIFT   4
#define HIDDEN  768
#define MROWS   (BATCH*LL)                 // 131072
#define NWINDOWS (BATCH*(HH/WS)*(WW_/WS))  // 2048
#define POS_DIM 12
#define POS_TAB 225

// ---------------------------------------------------------------------------
// Device scratch
// ---------------------------------------------------------------------------
__device__ __nv_bfloat16 gb_xw[(size_t)MROWS * CC];
__device__ __nv_bfloat16 gb_qkv[(size_t)MROWS * 3 * CC];
__device__ __nv_bfloat16 gb_attn[(size_t)MROWS * CC];
__device__ __nv_bfloat16 gb_ln2[(size_t)MROWS * CC];
__device__ __nv_bfloat16 gb_hid[(size_t)MROWS * HIDDEN];
__device__ float g_pos[POS_TAB * HEADS];
__device__ __nv_bfloat16 gb_wt_qkv[3 * CC * CC];
__device__ __nv_bfloat16 gb_wt_proj[CC * CC];
__device__ __nv_bfloat16 gb_wt_fc1[HIDDEN * CC];
__device__ __nv_bfloat16 gb_wt_fc2[CC * HIDDEN];

// ---------------------------------------------------------------------------
// Helpers
// ---------------------------------------------------------------------------
__device__ __forceinline__ uint32_t smem_u32(const void* p) {
    uint32_t a;
    asm("{ .reg .u64 t; cvta.to.shared.u64 t, %1; cvt.u32.u64 %0, t; }" : "=r"(a) : "l"(p));
    return a;
}
__device__ __forceinline__ void cpasync16(uint32_t s, const void* g) {
    asm volatile("cp.async.cg.shared.global [%0], [%1], 16;" :: "r"(s), "l"(g));
}
__device__ __forceinline__ void cp_commit() {
    asm volatile("cp.async.commit_group;" ::: "memory");
}
__device__ __forceinline__ void cp_wait1() {
    asm volatile("cp.async.wait_group 1;" ::: "memory");
}
__device__ __forceinline__ void ldsm_x4(uint32_t addr, uint32_t* r) {
    asm volatile("ldmatrix.sync.aligned.m8n8.x4.shared.b16 {%0,%1,%2,%3}, [%4];"
                 : "=r"(r[0]), "=r"(r[1]), "=r"(r[2]), "=r"(r[3]) : "r"(addr));
}
__device__ __forceinline__ void mma_bf16(float* d, const uint32_t* a, const uint32_t* b) {
    asm volatile(
        "mma.sync.aligned.m16n8k16.row.col.f32.bf16.bf16.f32 "
        "{%0,%1,%2,%3}, {%4,%5,%6,%7}, {%8,%9}, {%0,%1,%2,%3};"
        : "+f"(d[0]), "+f"(d[1]), "+f"(d[2]), "+f"(d[3])
        : "r"(a[0]), "r"(a[1]), "r"(a[2]), "r"(a[3]), "r"(b[0]), "r"(b[1]));
}
// packed f32x2 math (Blackwell FFMA2)
__device__ __forceinline__ float2 ffma2(float2 a, float2 b, float2 c) {
    unsigned long long ua = *(unsigned long long*)&a;
    unsigned long long ub = *(unsigned long long*)&b;
    unsigned long long uc = *(unsigned long long*)&c;
    unsigned long long ud;
    asm("fma.rn.f32x2 %0, %1, %2, %3;" : "=l"(ud) : "l"(ua), "l"(ub), "l"(uc));
    return *(float2*)&ud;
}
__device__ __forceinline__ float2 fmul2(float2 a, float2 b) {
    unsigned long long ua = *(unsigned long long*)&a;
    unsigned long long ub = *(unsigned long long*)&b;
    unsigned long long ud;
    asm("mul.rn.f32x2 %0, %1, %2;" : "=l"(ud) : "l"(ua), "l"(ub));
    return *(float2*)&ud;
}
// exact bf16x2 -> float2 via bit shifts (ALU pipe)
__device__ __forceinline__ float2 bf2f2(uint32_t u) {
    return make_float2(__uint_as_float(u << 16), __uint_as_float(u & 0xffff0000u));
}
__device__ __forceinline__ float gelu_exact(float x) {
    return 0.5f * x * (1.0f + erff(x * 0.7071067811865476f));
}

// ---------------------------------------------------------------------------
// Combined weight transpose: all 4 weights in one launch
// ---------------------------------------------------------------------------
#define TW_QKV (3*CC*CC)
#define TW_PROJ (CC*CC)
#define TW_FC1 (CC*HIDDEN)
#define TW_FC2 (HIDDEN*CC)
#define TW_TOTAL (TW_QKV + TW_PROJ + TW_FC1 + TW_FC2)

__global__ void transpose_all(const float* __restrict__ qkv_w, const float* __restrict__ proj_w,
                              const float* __restrict__ fc1_w, const float* __restrict__ fc2_w) {
    int i = blockIdx.x * 256 + threadIdx.x;
    if (i >= TW_TOTAL) return;
    const float* w; __nv_bfloat16* wt; int K, N, off;
    if (i < TW_QKV) { w = qkv_w; wt = gb_wt_qkv; K = CC; N = 3 * CC; off = i; }
    else if (i < TW_QKV + TW_PROJ) { w = proj_w; wt = gb_wt_proj; K = CC; N = CC; off = i - TW_QKV; }
    else if (i < TW_QKV + TW_PROJ + TW_FC1) { w = fc1_w; wt = gb_wt_fc1; K = CC; N = HIDDEN; off = i - TW_QKV - TW_PROJ; }
    else { w = fc2_w; wt = gb_wt_fc2; K = HIDDEN; N = CC; off = i - TW_QKV - TW_PROJ - TW_FC1; }
    int k = off / N, n = off % N;
    wt[(size_t)n * K + k] = __float2bfloat16(w[off]);
}

// ---------------------------------------------------------------------------
// Position-bias MLP
// ---------------------------------------------------------------------------
__device__ __forceinline__ void ln_relu12(const float* p, float* q,
                                          const float* g, const float* b) {
    float s = 0.f, s2 = 0.f;
#pragma unroll
    for (int i = 0; i < POS_DIM; i++) { s += p[i]; s2 += p[i] * p[i]; }
    float mu = s / 12.0f;
    float var = s2 / 12.0f - mu * mu;
    float rs = rsqrtf(var + 1e-5f);
#pragma unroll
    for (int i = 0; i < POS_DIM; i++) q[i] = fmaxf((p[i] - mu) * rs * g[i] + b[i], 0.0f);
}

__global__ void pos_mlp_kernel(
    const float* __restrict__ pp_w, const float* __restrict__ pp_b,
    const float* __restrict__ p1_g, const float* __restrict__ p1_b,
    const float* __restrict__ p1_w, const float* __restrict__ p1_bias,
    const float* __restrict__ p2_g, const float* __restrict__ p2_b,
    const float* __restrict__ p2_w, const float* __restrict__ p2_bias,
    const float* __restrict__ p3_g, const float* __restrict__ p3_b,
    const float* __restrict__ p3_w, const float* __restrict__ p3_bias) {
    int t = blockIdx.x * blockDim.x + threadIdx.x;
    if (t >= POS_TAB) return;
    float bh = (float)(t / 15 - 7), bw = (float)(t % 15 - 7);
    float p[POS_DIM], q[POS_DIM];
#pragma unroll
    for (int j = 0; j < POS_DIM; j++) p[j] = bh * pp_w[j] + bw * pp_w[POS_DIM + j] + pp_b[j];
    ln_relu12(p, q, p1_g, p1_b);
#pragma unroll
    for (int j = 0; j < POS_DIM; j++) {
        float s = p1_bias[j];
#pragma unroll
        for (int i = 0; i < POS_DIM; i++) s += q[i] * p1_w[i * POS_DIM + j];
        p[j] = s;
    }
    ln_relu12(p, q, p2_g, p2_b);
#pragma unroll
    for (int j = 0; j < POS_DIM; j++) {
        float s = p2_bias[j];
#pragma unroll
        for (int i = 0; i < POS_DIM; i++) s += q[i] * p2_w[i * POS_DIM + j];
        p[j] = s;
    }
    ln_relu12(p, q, p3_g, p3_b);
#pragma unroll
    for (int h = 0; h < HEADS; h++) {
        float s = p3_bias[h];
#pragma unroll
        for (int i = 0; i < POS_DIM; i++) s += q[i] * p3_w[i * HEADS + h];
        g_pos[t * HEADS + h] = s;
    }
}

// ---------------------------------------------------------------------------
// LayerNorm1 (C=192), warp per row, fp32 in -> bf16 out, shift+window gather
// ---------------------------------------------------------------------------
__global__ void __launch_bounds__(256) ln1_kernel(
    const float* __restrict__ in, __nv_bfloat16* __restrict__ out,
    const float* __restrict__ gamma, const float* __restrict__ beta) {
    int warp = threadIdx.x >> 5, lane = threadIdx.x & 31;
    int row = blockIdx.x * 8 + warp;
    int bb = row >> 14, rem = row & 16383;
    int win = rem >> 6, r = rem & 63;
    int wy = win >> 4, wx = win & 15, ry = r >> 3, rx = r & 7;
    int hh = (wy * WS + ry + SHIFT) & 127;
    int ww = (wx * WS + rx + SHIFT) & 127;
    size_t src = (size_t)bb * LL + hh * WW_ + ww;

    const float* p = in + src * CC;
    float v[6], s = 0.f, s2 = 0.f;
#pragma unroll
    for (int k = 0; k < 6; k++) { v[k] = p[lane + 32 * k]; s += v[k]; s2 += v[k] * v[k]; }
#pragma unroll
    for (int o = 16; o > 0; o >>= 1) {
        s += __shfl_xor_sync(0xFFFFFFFFu, s, o);
        s2 += __shfl_xor_sync(0xFFFFFFFFu, s2, o);
    }
    float mu = s * (1.0f / 192.0f);
    float rs = rsqrtf(s2 * (1.0f / 192.0f) - mu * mu + 1e-5f);
    __nv_bfloat16* q = out + (size_t)row * CC;
#pragma unroll
    for (int k = 0; k < 6; k++) {
        int c = lane + 32 * k;
        q[c] = __float2bfloat16((v[k] - mu) * rs * gamma[c] + beta[c]);
    }
}

// ---------------------------------------------------------------------------
// bf16 mma GEMM (generic): 128x64 tile, BK=64, ldmatrix, XOR-swizzled smem.
// EPI 0: +bias -> bf16   1: gelu(+bias) -> bf16   3: +bias +res -> fp32
// ---------------------------------------------------------------------------
#define CH_PER_BUF (192 * 8)

template <int EPI>
__global__ void __launch_bounds__(256) gemm_mma(
    const __nv_bfloat16* __restrict__ A, const __nv_bfloat16* __restrict__ BT,
    const float* __restrict__ bias, const float* __restrict__ res,
    void* __restrict__ outv, int K, int NOUT) {
    __shared__ __align__(16) uint4 smq[2 * CH_PER_BUF];
    uint32_t sbase = smem_u32(smq);
    int tid = threadIdx.x;
    int wid = tid >> 5, lane = tid & 31;
    int wm = wid & 3, wn = wid >> 2;
    int m0 = blockIdx.y * 128, n0 = blockIdx.x * 64;
    const __nv_bfloat16* Ab = A + (size_t)m0 * K;
    const __nv_bfloat16* Bb = BT + (size_t)n0 * K;
    int NCH = K >> 6;

    float acc[2][4][4];
#pragma unroll
    for (int i = 0; i < 2; i++)
#pragma unroll
        for (int j = 0; j < 4; j++)
#pragma unroll
            for (int k = 0; k < 4; k++) acc[i][j][k] = 0.f;

    int a_row = tid >> 1;
    int a_ch0 = (tid & 1) * 4;
    int b_row = tid >> 2;
    int b_ch0 = (tid & 3) * 2;

    int l15 = lane & 15, lhi = lane >> 4;
    int a_lrow = wm * 32 + l15;
    int a_sw = l15 & 7;
    int b_lrow = 128 + wn * 32 + (lhi << 3) + (lane & 7);
    int b_sw = lane & 7;
    int b_chlo = (lane >> 3) & 1;

    {
        uint32_t dst = sbase;
#pragma unroll
        for (int i = 0; i < 4; i++) {
            int ch = a_ch0 + i;
            cpasync16(dst + (a_row * 8 + (ch ^ (a_row & 7))) * 16,
                      Ab + (size_t)a_row * K + ch * 8);
        }
#pragma unroll
        for (int i = 0; i < 2; i++) {
            int ch = b_ch0 + i;
            cpasync16(dst + ((128 + b_row) * 8 + (ch ^ (b_row & 7))) * 16,
                      Bb + (size_t)b_row * K + ch * 8);
        }
        cp_commit();
    }

    for (int c = 0; c < NCH; c++) {
        if (c + 1 < NCH) {
            int k0 = (c + 1) << 6;
            uint32_t dst = sbase + ((c + 1) & 1) * CH_PER_BUF * 16;
#pragma unroll
            for (int i = 0; i < 4; i++) {
                int ch = a_ch0 + i;
                cpasync16(dst + (a_row * 8 + (ch ^ (a_row & 7))) * 16,
                          Ab + (size_t)a_row * K + k0 + ch * 8);
            }
#pragma unroll
            for (int i = 0; i < 2; i++) {
                int ch = b_ch0 + i;
                cpasync16(dst + ((128 + b_row) * 8 + (ch ^ (b_row & 7))) * 16,
                          Bb + (size_t)b_row * K + k0 + ch * 8);
            }
        }
        cp_commit();
        cp_wait1();
        __syncthreads();

        uint32_t buf = sbase + (c & 1) * CH_PER_BUF * 16;
#pragma unroll
        for (int ks = 0; ks < 4; ks++) {
            uint32_t a[2][4], b[2][4];
            int achk = 2 * ks + lhi;
#pragma unroll
            for (int mt = 0; mt < 2; mt++) {
                uint32_t idx = (a_lrow + mt * 16) * 8 + (achk ^ a_sw);
                ldsm_x4(buf + idx * 16, a[mt]);
            }
            int bchk = 2 * ks + b_chlo;
#pragma unroll
            for (int nt16 = 0; nt16 < 2; nt16++) {
                uint32_t idx = (b_lrow + nt16 * 16) * 8 + (bchk ^ b_sw);
                ldsm_x4(buf + idx * 16, b[nt16]);
            }
#pragma unroll
            for (int mt = 0; mt < 2; mt++) {
#pragma unroll
                for (int nt16 = 0; nt16 < 2; nt16++) {
                    mma_bf16(acc[mt][nt16 * 2 + 0], a[mt], &b[nt16][0]);
                    mma_bf16(acc[mt][nt16 * 2 + 1], a[mt], &b[nt16][2]);
                }
            }
        }
        __syncthreads();
    }

#pragma unroll
    for (int mt = 0; mt < 2; mt++) {
        int g0 = m0 + wm * 32 + mt * 16 + (lane >> 2);
        int g1 = g0 + 8;
        size_t ob0 = (size_t)g0 * NOUT;
        size_t ob1 = (size_t)g1 * NOUT;
#pragma unroll
        for (int nt = 0; nt < 4; nt++) {
            int col = n0 + wn * 32 + nt * 8 + 2 * (lane & 3);
            float b0 = bias[col], b1 = bias[col + 1];
            float2 v0 = make_float2(acc[mt][nt][0] + b0, acc[mt][nt][1] + b1);
            float2 v1 = make_float2(acc[mt][nt][2] + b0, acc[mt][nt][3] + b1);
            if (EPI == 1) {
                v0.x = gelu_exact(v0.x); v0.y = gelu_exact(v0.y);
                v1.x = gelu_exact(v1.x); v1.y = gelu_exact(v1.y);
            }
            if (EPI == 0 || EPI == 1) {
                __nv_bfloat16* out = (__nv_bfloat16*)outv;
                *(__nv_bfloat162*)(out + ob0 + col) = __float22bfloat162_rn(v0);
                *(__nv_bfloat162*)(out + ob1 + col) = __float22bfloat162_rn(v1);
            } else {
                float* out = (float*)outv;
                float2 r0 = *(const float2*)(res + ob0 + col);
                float2 r1 = *(const float2*)(res + ob1 + col);
                v0.x += r0.x; v0.y += r0.y;
                v1.x += r1.x; v1.y += r1.y;
                *(float2*)(out + ob0 + col) = v0;
                *(float2*)(out + ob1 + col) = v1;
            }
        }
    }
}

// ---------------------------------------------------------------------------
// Proj GEMM, full-row tile 128x192, fused: +bias, window-reverse scatter,
// +residual(x) -> y (fp32), then LN2 -> ln2 (bf16). K=192, N=192.
// 8 warps, each 16 rows x 192 cols; acc[24][4].
// SMEM rows: 0-127 A, 128-319 B; 8 chunks/row, XOR swizzle.
// ---------------------------------------------------------------------------
#define PCH_PER_BUF (320 * 8)
#define PROJ_SMEM (2 * PCH_PER_BUF * 16)

__global__ void __launch_bounds__(256) gemm_proj_ln(
    const __nv_bfloat16* __restrict__ A, const __nv_bfloat16* __restrict__ BT,
    const float* __restrict__ bias, const float* __restrict__ x,
    float* __restrict__ y, __nv_bfloat16* __restrict__ ln2out,
    const float* __restrict__ n2g, const float* __restrict__ n2b) {
    extern __shared__ __align__(16) uint4 psm[];
    uint32_t sbase = smem_u32(psm);
    int tid = threadIdx.x;
    int wid = tid >> 5, lane = tid & 31;
    int m0 = blockIdx.x * 128;
    const __nv_bfloat16* Ab = A + (size_t)m0 * CC;

    float acc[24][4];
#pragma unroll
    for (int j = 0; j < 24; j++)
#pragma unroll
        for (int k = 0; k < 4; k++) acc[j][k] = 0.f;

    int a_row = tid >> 1;
    int a_ch0 = (tid & 1) * 4;
    int b_row = tid >> 2;          // 0..63, 3 passes of 64 rows
    int b_ch0 = (tid & 3) * 2;

    int l15 = lane & 15, lhi = lane >> 4;
    int a_lrow = wid * 16 + l15;
    int a_sw = l15 & 7;
    int b_lbase = 128 + (lhi << 3) + (lane & 7);
    int b_sw = lane & 7;
    int b_chlo = (lane >> 3) & 1;

    // prologue chunk 0
    {
        uint32_t dst = sbase;
#pragma unroll
        for (int i = 0; i < 4; i++) {
            int ch = a_ch0 + i;
            cpasync16(dst + (a_row * 8 + (ch ^ (a_row & 7))) * 16,
                      Ab + (size_t)a_row * CC + ch * 8);
        }
#pragma unroll
        for (int r3 = 0; r3 < 3; r3++) {
            int row = r3 * 64 + b_row;
#pragma unroll
            for (int i = 0; i < 2; i++) {
                int ch = b_ch0 + i;
                cpasync16(dst + ((128 + row) * 8 + (ch ^ (row & 7))) * 16,
                          BT + (size_t)row * CC + ch * 8);
            }
        }
        cp_commit();
    }

    for (int c = 0; c < 3; c++) {
        if (c + 1 < 3) {
            int k0 = (c + 1) << 6;
            uint32_t dst = sbase + ((c + 1) & 1) * PCH_PER_BUF * 16;
#pragma unroll
            for (int i = 0; i < 4; i++) {
                int ch = a_ch0 + i;
                cpasync16(dst + (a_row * 8 + (ch ^ (a_row & 7))) * 16,
                          Ab + (size_t)a_row * CC + k0 + ch * 8);
            }
#pragma unroll
            for (int r3 = 0; r3 < 3; r3++) {
                int row = r3 * 64 + b_row;
#pragma unroll
                for (int i = 0; i < 2; i++) {
                    int ch = b_ch0 + i;
                    cpasync16(dst + ((128 + row) * 8 + (ch ^ (row & 7))) * 16,
                              BT + (size_t)row * CC + k0 + ch * 8);
                }
            }
        }
        cp_commit();
        cp_wait1();
        __syncthreads();

        uint32_t buf = sbase + (c & 1) * PCH_PER_BUF * 16;
#pragma unroll
        for (int ks = 0; ks < 4; ks++) {
            uint32_t a[4];
            int achk = 2 * ks + lhi;
            ldsm_x4(buf + (a_lrow * 8 + (achk ^ a_sw)) * 16, a);
            int bchk = 2 * ks + b_chlo;
#pragma unroll
            for (int nt16 = 0; nt16 < 12; nt16++) {
                uint32_t b[4];
                ldsm_x4(buf + ((b_lbase + nt16 * 16) * 8 + (bchk ^ b_sw)) * 16, b);
                mma_bf16(acc[nt16 * 2 + 0], a, &b[0]);
                mma_bf16(acc[nt16 * 2 + 1], a, &b[2]);
            }
        }
        __syncthreads();
    }

    // fused epilogue: scatter + residual + LN2
    int lq = lane & 3;
#pragma unroll
    for (int half = 0; half < 2; half++) {
        int g = m0 + wid * 16 + (lane >> 2) + half * 8;
        int bb = g >> 14, rem = g & 16383;
        int win = rem >> 6, rr = rem & 63;
        int wy = win >> 4, wx = win & 15, ry = rr >> 3, rx = rr & 7;
        int hh = (wy * WS + ry + SHIFT) & 127;
        int ww = (wx * WS + rx + SHIFT) & 127;
        size_t ob = ((size_t)bb * LL + hh * WW_ + ww) * CC;

        float vals[48];
        float s = 0.f, s2 = 0.f;
#pragma unroll
        for (int nt = 0; nt < 24; nt++) {
            int col = nt * 8 + 2 * lq;
            float v0 = acc[nt][half * 2 + 0] + bias[col];
            float v1 = acc[nt][half * 2 + 1] + bias[col + 1];
            float2 rv = *(const float2*)(x + ob + col);
            v0 += rv.x; v1 += rv.y;
            *(float2*)(y + ob + col) = make_float2(v0, v1);
            s += v0 + v1;
            s2 += v0 * v0 + v1 * v1;
            vals[nt * 2] = v0; vals[nt * 2 + 1] = v1;
        }
        s += __shfl_xor_sync(0xFFFFFFFFu, s, 1);
        s2 += __shfl_xor_sync(0xFFFFFFFFu, s2, 1);
        s += __shfl_xor_sync(0xFFFFFFFFu, s, 2);
        s2 += __shfl_xor_sync(0xFFFFFFFFu, s2, 2);
        float mu = s * (1.0f / 192.0f);
        float rs = rsqrtf(s2 * (1.0f / 192.0f) - mu * mu + 1e-5f);
#pragma unroll
        for (int nt = 0; nt < 24; nt++) {
            int col = nt * 8 + 2 * lq;
            float2 gg = *(const float2*)(n2g + col);
            float2 bb2 = *(const float2*)(n2b + col);
            float2 o;
            o.x = (vals[nt * 2] - mu) * rs * gg.x + bb2.x;
            o.y = (vals[nt * 2 + 1] - mu) * rs * gg.y + bb2.y;
            *(__nv_bfloat162*)(ln2out + ob + col) = __float22bfloat162_rn(o);
        }
    }
}

// ---------------------------------------------------------------------------
// Windowed attention: bf16 K/V in smem, fp32 online softmax, f32x2 FMA.
// ---------------------------------------------------------------------------
__global__ void __launch_bounds__(384) attn_kernel(
    const __nv_bfloat16* __restrict__ qkv, const float* __restrict__ pos,
    __nv_bfloat16* __restrict__ outp) {
    extern __shared__ __nv_bfloat16 smh[];
    __nv_bfloat16* k_s = smh;
    __nv_bfloat16* v_s = smh + NWIN * CC;

    int w = blockIdx.x;
    int tid = threadIdx.x;
    const __nv_bfloat16* base = qkv + (size_t)w * NWIN * (3 * CC);

    uint4* k4 = (uint4*)k_s;
    uint4* v4 = (uint4*)v_s;
    for (int idx = tid; idx < NWIN * 24; idx += 384) {
        int j = idx / 24, c = idx % 24;
        k4[j * 24 + c] = *(const uint4*)(base + (size_t)j * 576 + 192 + c * 8);
        v4[j * 24 + c] = *(const uint4*)(base + (size_t)j * 576 + 384 + c * 8);
    }
    __syncthreads();

    int h = tid / NWIN;
    int r = tid % NWIN;
    int ry = r >> 3, rx = r & 7;
    int winloc = w & 255;
    int wy = winloc >> 4, wx = winloc & 15;
    int lh_r = (wy == 15) ? (ry < (WS - SHIFT) ? 1 : 2) : 0;
    int lw_r = (wx == 15) ? (rx < (WS - SHIFT) ? 1 : 2) : 0;

    float2 q2[16];
    {
        const uint4* qp = (const uint4*)(base + (size_t)r * 576 + h * HD);
        float2 sc = make_float2(0.17677669529663687f, 0.17677669529663687f);
#pragma unroll
        for (int c = 0; c < 4; c++) {
            uint4 u = qp[c];
            q2[c * 4 + 0] = fmul2(bf2f2(u.x), sc);
            q2[c * 4 + 1] = fmul2(bf2f2(u.y), sc);
            q2[c * 4 + 2] = fmul2(bf2f2(u.z), sc);
            q2[c * 4 + 3] = fmul2(bf2f2(u.w), sc);
        }
    }

    const float* pb_ = pos + (((ry + 7) * 15) + (rx + 7)) * HEADS + h;
    const uint4* ks4 = (const uint4*)(k_s + h * HD);
    const uint4* vs4 = (const uint4*)(v_s + h * HD);

    float mx = -1e30f, sum = 0.f;
    float2 a2[16];
#pragma unroll
    for (int d = 0; d < 16; d++) a2[d] = make_float2(0.f, 0.f);

    for (int jy = 0; jy < 8; jy++) {
        int lh_j = (wy == 15) ? (jy < (WS - SHIFT) ? 1 : 2) : 0;
        bool hbad = (lh_j != lh_r);
        const float* pby = pb_ - jy * 90;
#pragma unroll
        for (int jx = 0; jx < 8; jx++) {
            int j = jy * 8 + jx;
            const uint4* kj = ks4 + j * 24;
            float2 sa = make_float2(0.f, 0.f), sb = make_float2(0.f, 0.f);
#pragma unroll
            for (int c = 0; c < 4; c++) {
                uint4 u = kj[c];
                sa = ffma2(q2[c * 4 + 0], bf2f2(u.x), sa);
                sb = ffma2(q2[c * 4 + 1], bf2f2(u.y), sb);
                sa = ffma2(q2[c * 4 + 2], bf2f2(u.z), sa);
                sb = ffma2(q2[c * 4 + 3], bf2f2(u.w), sb);
            }
            float s = (sa.x + sa.y) + (sb.x + sb.y);
            s += pby[-(jx * 6)];
            int lw_j = (wx == 15) ? (jx < (WS - SHIFT) ? 1 : 2) : 0;
            if (hbad || (lw_j != lw_r)) s -= 100.0f;

            float p;
            if (s > mx) {
                float cr = __expf(mx - s);
                mx = s;
                sum *= cr;
                float2 cr2 = make_float2(cr, cr);
#pragma unroll
                for (int d = 0; d < 16; d++) a2[d] = fmul2(cr2, a2[d]);
                p = 1.0f;
            } else {
                p = __expf(s - mx);
            }
            sum += p;
            float2 p2 = make_float2(p, p);
            const uint4* vj = vs4 + j * 24;
#pragma unroll
            for (int c = 0; c < 4; c++) {
                uint4 u = vj[c];
                a2[c * 4 + 0] = ffma2(p2, bf2f2(u.x), a2[c * 4 + 0]);
                a2[c * 4 + 1] = ffma2(p2, bf2f2(u.y), a2[c * 4 + 1]);
                a2[c * 4 + 2] = ffma2(p2, bf2f2(u.z), a2[c * 4 + 2]);
                a2[c * 4 + 3] = ffma2(p2, bf2f2(u.w), a2[c * 4 + 3]);
            }
        }
    }

    float inv = 1.0f / sum;
    float2 inv2 = make_float2(inv, inv);
    __nv_bfloat162* op = (__nv_bfloat162*)(outp + (size_t)(w * NWIN + r) * CC + h * HD);
#pragma unroll
    for (int d = 0; d < 16; d++) {
        op[d] = __float22bfloat162_rn(fmul2(a2[d], inv2));
    }
}

// ---------------------------------------------------------------------------
// Launch
// ---------------------------------------------------------------------------
extern "C" void kernel_launch(void* const* d_in, const int* in_sizes, int n_in,
                              void* d_out, int out_size) {
    const float* x      = (const float*)d_in[0];
    const float* n1_g   = (const float*)d_in[4];
    const float* n1_b   = (const float*)d_in[5];
    const float* qkv_w  = (const float*)d_in[6];
    const float* qkv_b  = (const float*)d_in[7];
    const float* proj_w = (const float*)d_in[8];
    const float* proj_b = (const float*)d_in[9];
    const float* pp_w   = (const float*)d_in[10];
    const float* pp_b   = (const float*)d_in[11];
    const float* p1_g   = (const float*)d_in[12];
    const float* p1_b   = (const float*)d_in[13];
    const float* p1_w   = (const float*)d_in[14];
    const float* p1_bi  = (const float*)d_in[15];
    const float* p2_g   = (const float*)d_in[16];
    const float* p2_b   = (const float*)d_in[17];
    const float* p2_w   = (const float*)d_in[18];
    const float* p2_bi  = (const float*)d_in[19];
    const float* p3_g   = (const float*)d_in[20];
    const float* p3_b   = (const float*)d_in[21];
    const float* p3_w   = (const float*)d_in[22];
    const float* p3_bi  = (const float*)d_in[23];
    const float* n2_g   = (const float*)d_in[24];
    const float* n2_b   = (const float*)d_in[25];
    const float* fc1_w  = (const float*)d_in[26];
    const float* fc1_b  = (const float*)d_in[27];
    const float* fc2_w  = (const float*)d_in[28];
    const float* fc2_b  = (const float*)d_in[29];
    float* out = (float*)d_out;

    __nv_bfloat16 *xw, *qkv, *attn, *ln2, *hid;
    __nv_bfloat16 *wt_qkv, *wt_proj, *wt_fc1, *wt_fc2;
    float* pos;
    cudaGetSymbolAddress((void**)&xw,   gb_xw);
    cudaGetSymbolAddress((void**)&qkv,  gb_qkv);
    cudaGetSymbolAddress((void**)&attn, gb_attn);
    cudaGetSymbolAddress((void**)&ln2,  gb_ln2);
    cudaGetSymbolAddress((void**)&hid,  gb_hid);
    cudaGetSymbolAddress((void**)&pos,  g_pos);
    cudaGetSymbolAddress((void**)&wt_qkv,  gb_wt_qkv);
    cudaGetSymbolAddress((void**)&wt_proj, gb_wt_proj);
    cudaGetSymbolAddress((void**)&wt_fc1,  gb_wt_fc1);
    cudaGetSymbolAddress((void**)&wt_fc2,  gb_wt_fc2);

    static bool attr_set = false;
    if (!attr_set) {
        cudaFuncSetAttribute(attn_kernel, cudaFuncAttributeMaxDynamicSharedMemorySize,
                             2 * NWIN * CC * (int)sizeof(__nv_bfloat16));
        cudaFuncSetAttribute(gemm_proj_ln, cudaFuncAttributeMaxDynamicSharedMemorySize,
                             PROJ_SMEM);
        attr_set = true;
    }

    // 0. all weight transposes in one launch
    transpose_all<<<(TW_TOTAL + 255) / 256, 256>>>(qkv_w, proj_w, fc1_w, fc2_w);

    // 1. position-bias MLP
    pos_mlp_kernel<<<1, 256>>>(pp_w, pp_b, p1_g, p1_b, p1_w, p1_bi,
                               p2_g, p2_b, p2_w, p2_bi, p3_g, p3_b, p3_w, p3_bi);

    // 2. LN1 + shift + window partition -> bf16
    ln1_kernel<<<MROWS / 8, 256>>>(x, xw, n1_g, n1_b);

    // 3. QKV GEMM -> bf16
    gemm_mma<0><<<dim3(576 / 64, MROWS / 128), 256>>>(xw, wt_qkv, qkv_b, nullptr, qkv, CC, 576);

    // 4. attention -> bf16
    attn_kernel<<<NWINDOWS, 384, 2 * NWIN * CC * (int)sizeof(__nv_bfloat16)>>>(qkv, pos, attn);

    // 5. proj + scatter + residual + LN2 (fused) -> y fp32 + ln2 bf16
    gemm_proj_ln<<<MROWS / 128, 256, PROJ_SMEM>>>(attn, wt_proj, proj_b, x, out, ln2, n2_g, n2_b);

    // 6. FC1 + GELU -> bf16
    gemm_mma<1><<<dim3(HIDDEN / 64, MROWS / 128), 256>>>(ln2, wt_fc1, fc1_b, nullptr, hid, CC, HIDDEN);

    // 7. FC2 + residual -> fp32 out
    gemm_mma<3><<<dim3(CC / 64, MROWS / 128), 256>>>(hid, wt_fc2, fc2_b, out, out, HIDDEN, CC);
}

// round 7
// speedup vs baseline: 4.7972x; 1.3235x over previous
#include <cuda_runtime.h>
#include <cuda_bf16.h>
#include <math.h>
#include <stdint.h>

// ---------------------------------------------------------------------------
// Problem constants
// ---------------------------------------------------------------------------
#define BATCH   8
#define HH      128
#define WW_     128
#define LL      (HH*WW_)
#define CC      192
#define HEADS   6
#define HD      32
#define WS      8
#define NWIN    64
#define SHIFT   4
#define HIDDEN  768
#define MROWS   (BATCH*LL)                 // 131072
#define NWINDOWS (BATCH*(HH/WS)*(WW_/WS))  // 2048
#define POS_DIM 12
#define POS_TAB 225
#define QSCALE  0.17677669529663687f

// ---------------------------------------------------------------------------
// Device scratch
// ---------------------------------------------------------------------------
__device__ __nv_bfloat16 gb_xw[(size_t)MROWS * CC];
__device__ __nv_bfloat16 gb_qkv[(size_t)MROWS * 3 * CC];
__device__ __nv_bfloat16 gb_attn[(size_t)MROWS * CC];
__device__ __nv_bfloat16 gb_ln2[(size_t)MROWS * CC];
__device__ __nv_bfloat16 gb_hid[(size_t)MROWS * HIDDEN];
__device__ float g_pos[POS_TAB * HEADS];
__device__ float g_bias[4 * HEADS * NWIN * NWIN];   // [type][h][r][j]
__device__ __nv_bfloat16 gb_wt_qkv[3 * CC * CC];
__device__ __nv_bfloat16 gb_wt_proj[CC * CC];
__device__ __nv_bfloat16 gb_wt_fc1[HIDDEN * CC];
__device__ __nv_bfloat16 gb_wt_fc2[CC * HIDDEN];

// ---------------------------------------------------------------------------
// Helpers
// ---------------------------------------------------------------------------
__device__ __forceinline__ uint32_t smem_u32(const void* p) {
    uint32_t a;
    asm("{ .reg .u64 t; cvta.to.shared.u64 t, %1; cvt.u32.u64 %0, t; }" : "=r"(a) : "l"(p));
    return a;
}
__device__ __forceinline__ void cpasync16(uint32_t s, const void* g) {
    asm volatile("cp.async.cg.shared.global [%0], [%1], 16;" :: "r"(s), "l"(g));
}
__device__ __forceinline__ void cp_commit() {
    asm volatile("cp.async.commit_group;" ::: "memory");
}
__device__ __forceinline__ void cp_wait1() {
    asm volatile("cp.async.wait_group 1;" ::: "memory");
}
__device__ __forceinline__ void ldsm_x4(uint32_t addr, uint32_t* r) {
    asm volatile("ldmatrix.sync.aligned.m8n8.x4.shared.b16 {%0,%1,%2,%3}, [%4];"
                 : "=r"(r[0]), "=r"(r[1]), "=r"(r[2]), "=r"(r[3]) : "r"(addr));
}
__device__ __forceinline__ void mma_bf16(float* d, const uint32_t* a, const uint32_t* b) {
    asm volatile(
        "mma.sync.aligned.m16n8k16.row.col.f32.bf16.bf16.f32 "
        "{%0,%1,%2,%3}, {%4,%5,%6,%7}, {%8,%9}, {%0,%1,%2,%3};"
        : "+f"(d[0]), "+f"(d[1]), "+f"(d[2]), "+f"(d[3])
        : "r"(a[0]), "r"(a[1]), "r"(a[2]), "r"(a[3]), "r"(b[0]), "r"(b[1]));
}
__device__ __forceinline__ uint32_t packbf2(float x, float y) {
    __nv_bfloat162 t = __float22bfloat162_rn(make_float2(x, y));
    return *(uint32_t*)&t;
}
__device__ __forceinline__ float gelu_exact(float x) {
    return 0.5f * x * (1.0f + erff(x * 0.7071067811865476f));
}

// ---------------------------------------------------------------------------
// Combined weight transpose
// ---------------------------------------------------------------------------
#define TW_QKV (3*CC*CC)
#define TW_PROJ (CC*CC)
#define TW_FC1 (CC*HIDDEN)
#define TW_FC2 (HIDDEN*CC)
#define TW_TOTAL (TW_QKV + TW_PROJ + TW_FC1 + TW_FC2)

__global__ void transpose_all(const float* __restrict__ qkv_w, const float* __restrict__ proj_w,
                              const float* __restrict__ fc1_w, const float* __restrict__ fc2_w) {
    int i = blockIdx.x * 256 + threadIdx.x;
    if (i >= TW_TOTAL) return;
    const float* w; __nv_bfloat16* wt; int K, N, off;
    if (i < TW_QKV) { w = qkv_w; wt = gb_wt_qkv; K = CC; N = 3 * CC; off = i; }
    else if (i < TW_QKV + TW_PROJ) { w = proj_w; wt = gb_wt_proj; K = CC; N = CC; off = i - TW_QKV; }
    else if (i < TW_QKV + TW_PROJ + TW_FC1) { w = fc1_w; wt = gb_wt_fc1; K = CC; N = HIDDEN; off = i - TW_QKV - TW_PROJ; }
    else { w = fc2_w; wt = gb_wt_fc2; K = HIDDEN; N = CC; off = i - TW_QKV - TW_PROJ - TW_FC1; }
    int k = off / N, n = off % N;
    wt[(size_t)n * K + k] = __float2bfloat16(w[off]);
}

// ---------------------------------------------------------------------------
// Position-bias MLP
// ---------------------------------------------------------------------------
__device__ __forceinline__ void ln_relu12(const float* p, float* q,
                                          const float* g, const float* b) {
    float s = 0.f, s2 = 0.f;
#pragma unroll
    for (int i = 0; i < POS_DIM; i++) { s += p[i]; s2 += p[i] * p[i]; }
    float mu = s / 12.0f;
    float var = s2 / 12.0f - mu * mu;
    float rs = rsqrtf(var + 1e-5f);
#pragma unroll
    for (int i = 0; i < POS_DIM; i++) q[i] = fmaxf((p[i] - mu) * rs * g[i] + b[i], 0.0f);
}

__global__ void pos_mlp_kernel(
    const float* __restrict__ pp_w, const float* __restrict__ pp_b,
    const float* __restrict__ p1_g, const float* __restrict__ p1_b,
    const float* __restrict__ p1_w, const float* __restrict__ p1_bias,
    const float* __restrict__ p2_g, const float* __restrict__ p2_b,
    const float* __restrict__ p2_w, const float* __restrict__ p2_bias,
    const float* __restrict__ p3_g, const float* __restrict__ p3_b,
    const float* __restrict__ p3_w, const float* __restrict__ p3_bias) {
    int t = blockIdx.x * blockDim.x + threadIdx.x;
    if (t >= POS_TAB) return;
    float bh = (float)(t / 15 - 7), bw = (float)(t % 15 - 7);
    float p[POS_DIM], q[POS_DIM];
#pragma unroll
    for (int j = 0; j < POS_DIM; j++) p[j] = bh * pp_w[j] + bw * pp_w[POS_DIM + j] + pp_b[j];
    ln_relu12(p, q, p1_g, p1_b);
#pragma unroll
    for (int j = 0; j < POS_DIM; j++) {
        float s = p1_bias[j];
#pragma unroll
        for (int i = 0; i < POS_DIM; i++) s += q[i] * p1_w[i * POS_DIM + j];
        p[j] = s;
    }
    ln_relu12(p, q, p2_g, p2_b);
#pragma unroll
    for (int j = 0; j < POS_DIM; j++) {
        float s = p2_bias[j];
#pragma unroll
        for (int i = 0; i < POS_DIM; i++) s += q[i] * p2_w[i * POS_DIM + j];
        p[j] = s;
    }
    ln_relu12(p, q, p3_g, p3_b);
#pragma unroll
    for (int h = 0; h < HEADS; h++) {
        float s = p3_bias[h];
#pragma unroll
        for (int i = 0; i < POS_DIM; i++) s += q[i] * p3_w[i * HEADS + h];
        g_pos[t * HEADS + h] = s;
    }
}

// ---------------------------------------------------------------------------
// Bias table: [type][h][r][j] = pos(rel) + mask. type = (wy==15)*2 | (wx==15)
// ---------------------------------------------------------------------------
__global__ void bias_build() {
    int idx = blockIdx.x * 256 + threadIdx.x;
    if (idx >= 4 * HEADS * NWIN * NWIN) return;
    int j = idx & 63;
    int r = (idx >> 6) & 63;
    int h = (idx >> 12) % HEADS;
    int t = idx / (HEADS * NWIN * NWIN);
    int ry = r >> 3, rx = r & 7, jy = j >> 3, jx = j & 7;
    float bias = g_pos[(((ry - jy + 7) * 15) + (rx - jx + 7)) * HEADS + h];
    int lhr = (t & 2) ? (ry < (WS - SHIFT) ? 1 : 2) : 0;
    int lhj = (t & 2) ? (jy < (WS - SHIFT) ? 1 : 2) : 0;
    int lwr = (t & 1) ? (rx < (WS - SHIFT) ? 1 : 2) : 0;
    int lwj = (t & 1) ? (jx < (WS - SHIFT) ? 1 : 2) : 0;
    if (lhr != lhj || lwr != lwj) bias -= 100.0f;
    g_bias[idx] = bias;
}

// ---------------------------------------------------------------------------
// LayerNorm1: warp per row, fp32 in -> bf16 out, shift+window gather
// ---------------------------------------------------------------------------
__global__ void __launch_bounds__(256) ln1_kernel(
    const float* __restrict__ in, __nv_bfloat16* __restrict__ out,
    const float* __restrict__ gamma, const float* __restrict__ beta) {
    int warp = threadIdx.x >> 5, lane = threadIdx.x & 31;
    int row = blockIdx.x * 8 + warp;
    int bb = row >> 14, rem = row & 16383;
    int win = rem >> 6, r = rem & 63;
    int wy = win >> 4, wx = win & 15, ry = r >> 3, rx = r & 7;
    int hh = (wy * WS + ry + SHIFT) & 127;
    int ww = (wx * WS + rx + SHIFT) & 127;
    size_t src = (size_t)bb * LL + hh * WW_ + ww;

    const float* p = in + src * CC;
    float v[6], s = 0.f, s2 = 0.f;
#pragma unroll
    for (int k = 0; k < 6; k++) { v[k] = p[lane + 32 * k]; s += v[k]; s2 += v[k] * v[k]; }
#pragma unroll
    for (int o = 16; o > 0; o >>= 1) {
        s += __shfl_xor_sync(0xFFFFFFFFu, s, o);
        s2 += __shfl_xor_sync(0xFFFFFFFFu, s2, o);
    }
    float mu = s * (1.0f / 192.0f);
    float rs = rsqrtf(s2 * (1.0f / 192.0f) - mu * mu + 1e-5f);
    __nv_bfloat16* q = out + (size_t)row * CC;
#pragma unroll
    for (int k = 0; k < 6; k++) {
        int c = lane + 32 * k;
        q[c] = __float2bfloat16((v[k] - mu) * rs * gamma[c] + beta[c]);
    }
}

// ---------------------------------------------------------------------------
// bf16 mma GEMM (generic): 128x64 tile, BK=64, ldmatrix, XOR-swizzled smem.
// EPI 0: +bias, scale cols<192 (Q) -> bf16   1: gelu(+bias) -> bf16
// EPI 3: +bias +res -> fp32
// ---------------------------------------------------------------------------
#define CH_PER_BUF (192 * 8)

template <int EPI>
__global__ void __launch_bounds__(256) gemm_mma(
    const __nv_bfloat16* __restrict__ A, const __nv_bfloat16* __restrict__ BT,
    const float* __restrict__ bias, const float* __restrict__ res,
    void* __restrict__ outv, int K, int NOUT) {
    __shared__ __align__(16) uint4 smq[2 * CH_PER_BUF];
    uint32_t sbase = smem_u32(smq);
    int tid = threadIdx.x;
    int wid = tid >> 5, lane = tid & 31;
    int wm = wid & 3, wn = wid >> 2;
    int m0 = blockIdx.y * 128, n0 = blockIdx.x * 64;
    const __nv_bfloat16* Ab = A + (size_t)m0 * K;
    const __nv_bfloat16* Bb = BT + (size_t)n0 * K;
    int NCH = K >> 6;

    float acc[2][4][4];
#pragma unroll
    for (int i = 0; i < 2; i++)
#pragma unroll
        for (int j = 0; j < 4; j++)
#pragma unroll
            for (int k = 0; k < 4; k++) acc[i][j][k] = 0.f;

    int a_row = tid >> 1;
    int a_ch0 = (tid & 1) * 4;
    int b_row = tid >> 2;
    int b_ch0 = (tid & 3) * 2;

    int l15 = lane & 15, lhi = lane >> 4;
    int a_lrow = wm * 32 + l15;
    int a_sw = l15 & 7;
    int b_lrow = 128 + wn * 32 + (lhi << 3) + (lane & 7);
    int b_sw = lane & 7;
    int b_chlo = (lane >> 3) & 1;

    {
        uint32_t dst = sbase;
#pragma unroll
        for (int i = 0; i < 4; i++) {
            int ch = a_ch0 + i;
            cpasync16(dst + (a_row * 8 + (ch ^ (a_row & 7))) * 16,
                      Ab + (size_t)a_row * K + ch * 8);
        }
#pragma unroll
        for (int i = 0; i < 2; i++) {
            int ch = b_ch0 + i;
            cpasync16(dst + ((128 + b_row) * 8 + (ch ^ (b_row & 7))) * 16,
                      Bb + (size_t)b_row * K + ch * 8);
        }
        cp_commit();
    }

    for (int c = 0; c < NCH; c++) {
        if (c + 1 < NCH) {
            int k0 = (c + 1) << 6;
            uint32_t dst = sbase + ((c + 1) & 1) * CH_PER_BUF * 16;
#pragma unroll
            for (int i = 0; i < 4; i++) {
                int ch = a_ch0 + i;
                cpasync16(dst + (a_row * 8 + (ch ^ (a_row & 7))) * 16,
                          Ab + (size_t)a_row * K + k0 + ch * 8);
            }
#pragma unroll
            for (int i = 0; i < 2; i++) {
                int ch = b_ch0 + i;
                cpasync16(dst + ((128 + b_row) * 8 + (ch ^ (b_row & 7))) * 16,
                          Bb + (size_t)b_row * K + k0 + ch * 8);
            }
        }
        cp_commit();
        cp_wait1();
        __syncthreads();

        uint32_t buf = sbase + (c & 1) * CH_PER_BUF * 16;
#pragma unroll
        for (int ks = 0; ks < 4; ks++) {
            uint32_t a[2][4], b[2][4];
            int achk = 2 * ks + lhi;
#pragma unroll
            for (int mt = 0; mt < 2; mt++) {
                uint32_t idx = (a_lrow + mt * 16) * 8 + (achk ^ a_sw);
                ldsm_x4(buf + idx * 16, a[mt]);
            }
            int bchk = 2 * ks + b_chlo;
#pragma unroll
            for (int nt16 = 0; nt16 < 2; nt16++) {
                uint32_t idx = (b_lrow + nt16 * 16) * 8 + (bchk ^ b_sw);
                ldsm_x4(buf + idx * 16, b[nt16]);
            }
#pragma unroll
            for (int mt = 0; mt < 2; mt++) {
#pragma unroll
                for (int nt16 = 0; nt16 < 2; nt16++) {
                    mma_bf16(acc[mt][nt16 * 2 + 0], a[mt], &b[nt16][0]);
                    mma_bf16(acc[mt][nt16 * 2 + 1], a[mt], &b[nt16][2]);
                }
            }
        }
        __syncthreads();
    }

#pragma unroll
    for (int mt = 0; mt < 2; mt++) {
        int g0 = m0 + wm * 32 + mt * 16 + (lane >> 2);
        int g1 = g0 + 8;
        size_t ob0 = (size_t)g0 * NOUT;
        size_t ob1 = (size_t)g1 * NOUT;
#pragma unroll
        for (int nt = 0; nt < 4; nt++) {
            int col = n0 + wn * 32 + nt * 8 + 2 * (lane & 3);
            float b0 = bias[col], b1 = bias[col + 1];
            float2 v0 = make_float2(acc[mt][nt][0] + b0, acc[mt][nt][1] + b1);
            float2 v1 = make_float2(acc[mt][nt][2] + b0, acc[mt][nt][3] + b1);
            if (EPI == 0) {
                float sc = (col < CC) ? QSCALE : 1.0f;
                v0.x *= sc; v0.y *= sc; v1.x *= sc; v1.y *= sc;
            }
            if (EPI == 1) {
                v0.x = gelu_exact(v0.x); v0.y = gelu_exact(v0.y);
                v1.x = gelu_exact(v1.x); v1.y = gelu_exact(v1.y);
            }
            if (EPI == 0 || EPI == 1) {
                __nv_bfloat16* out = (__nv_bfloat16*)outv;
                *(__nv_bfloat162*)(out + ob0 + col) = __float22bfloat162_rn(v0);
                *(__nv_bfloat162*)(out + ob1 + col) = __float22bfloat162_rn(v1);
            } else {
                float* out = (float*)outv;
                float2 r0 = *(const float2*)(res + ob0 + col);
                float2 r1 = *(const float2*)(res + ob1 + col);
                v0.x += r0.x; v0.y += r0.y;
                v1.x += r1.x; v1.y += r1.y;
                *(float2*)(out + ob0 + col) = v0;
                *(float2*)(out + ob1 + col) = v1;
            }
        }
    }
}

// ---------------------------------------------------------------------------
// Proj GEMM + scatter + residual + LN2 (fused), unchanged from round 6.
// ---------------------------------------------------------------------------
#define PCH_PER_BUF (320 * 8)
#define PROJ_SMEM (2 * PCH_PER_BUF * 16)

__global__ void __launch_bounds__(256) gemm_proj_ln(
    const __nv_bfloat16* __restrict__ A, const __nv_bfloat16* __restrict__ BT,
    const float* __restrict__ bias, const float* __restrict__ x,
    float* __restrict__ y, __nv_bfloat16* __restrict__ ln2out,
    const float* __restrict__ n2g, const float* __restrict__ n2b) {
    extern __shared__ __align__(16) uint4 psm[];
    uint32_t sbase = smem_u32(psm);
    int tid = threadIdx.x;
    int wid = tid >> 5, lane = tid & 31;
    int m0 = blockIdx.x * 128;
    const __nv_bfloat16* Ab = A + (size_t)m0 * CC;

    float acc[24][4];
#pragma unroll
    for (int j = 0; j < 24; j++)
#pragma unroll
        for (int k = 0; k < 4; k++) acc[j][k] = 0.f;

    int a_row = tid >> 1;
    int a_ch0 = (tid & 1) * 4;
    int b_row = tid >> 2;
    int b_ch0 = (tid & 3) * 2;

    int l15 = lane & 15, lhi = lane >> 4;
    int a_lrow = wid * 16 + l15;
    int a_sw = l15 & 7;
    int b_lbase = 128 + (lhi << 3) + (lane & 7);
    int b_sw = lane & 7;
    int b_chlo = (lane >> 3) & 1;

    {
        uint32_t dst = sbase;
#pragma unroll
        for (int i = 0; i < 4; i++) {
            int ch = a_ch0 + i;
            cpasync16(dst + (a_row * 8 + (ch ^ (a_row & 7))) * 16,
                      Ab + (size_t)a_row * CC + ch * 8);
        }
#pragma unroll
        for (int r3 = 0; r3 < 3; r3++) {
            int row = r3 * 64 + b_row;
#pragma unroll
            for (int i = 0; i < 2; i++) {
                int ch = b_ch0 + i;
                cpasync16(dst + ((128 + row) * 8 + (ch ^ (row & 7))) * 16,
                          BT + (size_t)row * CC + ch * 8);
            }
        }
        cp_commit();
    }

    for (int c = 0; c < 3; c++) {
        if (c + 1 < 3) {
            int k0 = (c + 1) << 6;
            uint32_t dst = sbase + ((c + 1) & 1) * PCH_PER_BUF * 16;
#pragma unroll
            for (int i = 0; i < 4; i++) {
                int ch = a_ch0 + i;
                cpasync16(dst + (a_row * 8 + (ch ^ (a_row & 7))) * 16,
                          Ab + (size_t)a_row * CC + k0 + ch * 8);
            }
#pragma unroll
            for (int r3 = 0; r3 < 3; r3++) {
                int row = r3 * 64 + b_row;
#pragma unroll
                for (int i = 0; i < 2; i++) {
                    int ch = b_ch0 + i;
                    cpasync16(dst + ((128 + row) * 8 + (ch ^ (row & 7))) * 16,
                              BT + (size_t)row * CC + k0 + ch * 8);
                }
            }
        }
        cp_commit();
        cp_wait1();
        __syncthreads();

        uint32_t buf = sbase + (c & 1) * PCH_PER_BUF * 16;
#pragma unroll
        for (int ks = 0; ks < 4; ks++) {
            uint32_t a[4];
            int achk = 2 * ks + lhi;
            ldsm_x4(buf + (a_lrow * 8 + (achk ^ a_sw)) * 16, a);
            int bchk = 2 * ks + b_chlo;
#pragma unroll
            for (int nt16 = 0; nt16 < 12; nt16++) {
                uint32_t b[4];
                ldsm_x4(buf + ((b_lbase + nt16 * 16) * 8 + (bchk ^ b_sw)) * 16, b);
                mma_bf16(acc[nt16 * 2 + 0], a, &b[0]);
                mma_bf16(acc[nt16 * 2 + 1], a, &b[2]);
            }
        }
        __syncthreads();
    }

    int lq = lane & 3;
#pragma unroll
    for (int half = 0; half < 2; half++) {
        int g = m0 + wid * 16 + (lane >> 2) + half * 8;
        int bb = g >> 14, rem = g & 16383;
        int win = rem >> 6, rr = rem & 63;
        int wy = win >> 4, wx = win & 15, ry = rr >> 3, rx = rr & 7;
        int hh = (wy * WS + ry + SHIFT) & 127;
        int ww = (wx * WS + rx + SHIFT) & 127;
        size_t ob = ((size_t)bb * LL + hh * WW_ + ww) * CC;

        float vals[48];
        float s = 0.f, s2 = 0.f;
#pragma unroll
        for (int nt = 0; nt < 24; nt++) {
            int col = nt * 8 + 2 * lq;
            float v0 = acc[nt][half * 2 + 0] + bias[col];
            float v1 = acc[nt][half * 2 + 1] + bias[col + 1];
            float2 rv = *(const float2*)(x + ob + col);
            v0 += rv.x; v1 += rv.y;
            *(float2*)(y + ob + col) = make_float2(v0, v1);
            s += v0 + v1;
            s2 += v0 * v0 + v1 * v1;
            vals[nt * 2] = v0; vals[nt * 2 + 1] = v1;
        }
        s += __shfl_xor_sync(0xFFFFFFFFu, s, 1);
        s2 += __shfl_xor_sync(0xFFFFFFFFu, s2, 1);
        s += __shfl_xor_sync(0xFFFFFFFFu, s, 2);
        s2 += __shfl_xor_sync(0xFFFFFFFFu, s2, 2);
        float mu = s * (1.0f / 192.0f);
        float rs = rsqrtf(s2 * (1.0f / 192.0f) - mu * mu + 1e-5f);
#pragma unroll
        for (int nt = 0; nt < 24; nt++) {
            int col = nt * 8 + 2 * lq;
            float2 gg = *(const float2*)(n2g + col);
            float2 bb2 = *(const float2*)(n2b + col);
            float2 o;
            o.x = (vals[nt * 2] - mu) * rs * gg.x + bb2.x;
            o.y = (vals[nt * 2 + 1] - mu) * rs * gg.y + bb2.y;
            *(__nv_bfloat162*)(ln2out + ob + col) = __float22bfloat162_rn(o);
        }
    }
}

// ---------------------------------------------------------------------------
// Tensor-core windowed attention. 1 CTA/window, 12 warps = (head, 32-row half).
// K staged [key][dim] stride 200; V staged transposed [dim][key] stride 72.
// S = Qs @ K^T via mma (Q pre-scaled in QKV epilogue), bias from g_bias table,
// softmax in registers, P repacked to A-frags, O = P @ V^T-smem via mma.
// ---------------------------------------------------------------------------
#define KSTR 200
#define VSTR 72
#define ATTN_SMEM ((NWIN * KSTR + CC * VSTR) * 2)

__global__ void __launch_bounds__(384) attn_kernel(
    const __nv_bfloat16* __restrict__ qkv, __nv_bfloat16* __restrict__ outp) {
    extern __shared__ __nv_bfloat16 smh[];
    __nv_bfloat16* k_s = smh;                 // [64][KSTR]
    __nv_bfloat16* vt_s = smh + NWIN * KSTR;  // [192][VSTR]

    int w = blockIdx.x;
    int tid = threadIdx.x;
    int lane = tid & 31, wid = tid >> 5;
    const __nv_bfloat16* base = qkv + (size_t)w * NWIN * 576;

    // stage K (rows) and V (transposed, rotated scalar stores)
    for (int idx = tid; idx < NWIN * 24; idx += 384) {
        int j = idx / 24, c = idx % 24;
        uint4 uk = *(const uint4*)(base + (size_t)j * 576 + 192 + c * 8);
        *(uint4*)(k_s + j * KSTR + c * 8) = uk;
        uint4 uv = *(const uint4*)(base + (size_t)j * 576 + 384 + c * 8);
        const unsigned short* e = (const unsigned short*)&uv;
#pragma unroll
        for (int i = 0; i < 8; i++) {
            int k = (i + lane) & 7;
            *((unsigned short*)vt_s + (c * 8 + k) * VSTR + j) = e[k];
        }
    }
    __syncthreads();

    int h = wid >> 1;
    int mbase = (wid & 1) * 32;
    int winloc = w & 255;
    int wy = winloc >> 4, wx = winloc & 15;
    int type = ((wy == 15) ? 2 : 0) | ((wx == 15) ? 1 : 0);
    const float* btab = g_bias + ((size_t)(type * HEADS + h) * NWIN) * NWIN;

    int rq = lane >> 2, cq = 2 * (lane & 3);
    int brow = ((lane >> 4) << 3) + (lane & 7);
    int bchlo = (lane >> 3) & 1;

    // A fragments (Q) direct from global (Q pre-scaled)
    uint32_t a[2][2][4];
#pragma unroll
    for (int mt = 0; mt < 2; mt++)
#pragma unroll
        for (int ks = 0; ks < 2; ks++)
#pragma unroll
            for (int i = 0; i < 4; i++) {
                int row = mbase + mt * 16 + rq + (i & 1) * 8;
                int col = h * HD + ks * 16 + cq + (i >> 1) * 8;
                a[mt][ks][i] = *(const uint32_t*)(base + (size_t)row * 576 + col);
            }

    // S = Q @ K^T
    float p[2][8][4];
#pragma unroll
    for (int i = 0; i < 2; i++)
#pragma unroll
        for (int j = 0; j < 8; j++)
#pragma unroll
            for (int k = 0; k < 4; k++) p[i][j][k] = 0.f;

    uint32_t ksm = smem_u32(k_s);
#pragma unroll
    for (int kg = 0; kg < 4; kg++) {
#pragma unroll
        for (int ks = 0; ks < 2; ks++) {
            uint32_t b[4];
            uint32_t addr = ksm + ((kg * 16 + brow) * KSTR + (h * 4 + ks * 2 + bchlo) * 8) * 2;
            ldsm_x4(addr, b);
#pragma unroll
            for (int mt = 0; mt < 2; mt++) {
                mma_bf16(p[mt][kg * 2 + 0], a[mt][ks], &b[0]);
                mma_bf16(p[mt][kg * 2 + 1], a[mt][ks], &b[2]);
            }
        }
    }

    // bias + softmax (rows r and r+8 per mt)
    float sums[2][2];
#pragma unroll
    for (int mt = 0; mt < 2; mt++) {
#pragma unroll
        for (int rl = 0; rl < 2; rl++) {
            int r = mbase + mt * 16 + rq + rl * 8;
            const float* br_ = btab + r * NWIN;
            float m = -1e30f;
#pragma unroll
            for (int nt = 0; nt < 8; nt++) {
                float2 bv = *(const float2*)(br_ + nt * 8 + cq);
                p[mt][nt][rl * 2 + 0] += bv.x;
                p[mt][nt][rl * 2 + 1] += bv.y;
                m = fmaxf(m, fmaxf(p[mt][nt][rl * 2], p[mt][nt][rl * 2 + 1]));
            }
            m = fmaxf(m, __shfl_xor_sync(0xFFFFFFFFu, m, 1));
            m = fmaxf(m, __shfl_xor_sync(0xFFFFFFFFu, m, 2));
            float s = 0.f;
#pragma unroll
            for (int nt = 0; nt < 8; nt++) {
                float e0 = __expf(p[mt][nt][rl * 2] - m);
                float e1 = __expf(p[mt][nt][rl * 2 + 1] - m);
                p[mt][nt][rl * 2] = e0; p[mt][nt][rl * 2 + 1] = e1;
                s += e0 + e1;
            }
            s += __shfl_xor_sync(0xFFFFFFFFu, s, 1);
            s += __shfl_xor_sync(0xFFFFFFFFu, s, 2);
            sums[mt][rl] = s;
        }
    }

    // pack P to bf16 A-fragments
    uint32_t pa[2][4][4];
#pragma unroll
    for (int mt = 0; mt < 2; mt++)
#pragma unroll
        for (int s4 = 0; s4 < 4; s4++) {
            pa[mt][s4][0] = packbf2(p[mt][2 * s4][0], p[mt][2 * s4][1]);
            pa[mt][s4][1] = packbf2(p[mt][2 * s4][2], p[mt][2 * s4][3]);
            pa[mt][s4][2] = packbf2(p[mt][2 * s4 + 1][0], p[mt][2 * s4 + 1][1]);
            pa[mt][s4][3] = packbf2(p[mt][2 * s4 + 1][2], p[mt][2 * s4 + 1][3]);
        }

    // O = P @ V (V^T in smem, same B pattern as K)
    float o[2][4][4];
#pragma unroll
    for (int i = 0; i < 2; i++)
#pragma unroll
        for (int j = 0; j < 4; j++)
#pragma unroll
            for (int k = 0; k < 4; k++) o[i][j][k] = 0.f;

    uint32_t vsm = smem_u32(vt_s);
#pragma unroll
    for (int s4 = 0; s4 < 4; s4++) {
#pragma unroll
        for (int n16 = 0; n16 < 2; n16++) {
            uint32_t b[4];
            uint32_t addr = vsm + ((h * HD + n16 * 16 + brow) * VSTR + (s4 * 2 + bchlo) * 8) * 2;
            ldsm_x4(addr, b);
#pragma unroll
            for (int mt = 0; mt < 2; mt++) {
                mma_bf16(o[mt][n16 * 2 + 0], pa[mt][s4], &b[0]);
                mma_bf16(o[mt][n16 * 2 + 1], pa[mt][s4], &b[2]);
            }
        }
    }

    // normalize + store
#pragma unroll
    for (int mt = 0; mt < 2; mt++) {
        float i0 = 1.0f / sums[mt][0];
        float i1 = 1.0f / sums[mt][1];
        int r0 = mbase + mt * 16 + rq;
        __nv_bfloat16* op0 = outp + (size_t)(w * NWIN + r0) * CC + h * HD;
        __nv_bfloat16* op1 = op0 + 8 * CC;
#pragma unroll
        for (int nt = 0; nt < 4; nt++) {
            *(__nv_bfloat162*)(op0 + nt * 8 + cq) =
                __float22bfloat162_rn(make_float2(o[mt][nt][0] * i0, o[mt][nt][1] * i0));
            *(__nv_bfloat162*)(op1 + nt * 8 + cq) =
                __float22bfloat162_rn(make_float2(o[mt][nt][2] * i1, o[mt][nt][3] * i1));
        }
    }
}

// ---------------------------------------------------------------------------
// Launch
// ---------------------------------------------------------------------------
extern "C" void kernel_launch(void* const* d_in, const int* in_sizes, int n_in,
                              void* d_out, int out_size) {
    const float* x      = (const float*)d_in[0];
    const float* n1_g   = (const float*)d_in[4];
    const float* n1_b   = (const float*)d_in[5];
    const float* qkv_w  = (const float*)d_in[6];
    const float* qkv_b  = (const float*)d_in[7];
    const float* proj_w = (const float*)d_in[8];
    const float* proj_b = (const float*)d_in[9];
    const float* pp_w   = (const float*)d_in[10];
    const float* pp_b   = (const float*)d_in[11];
    const float* p1_g   = (const float*)d_in[12];
    const float* p1_b   = (const float*)d_in[13];
    const float* p1_w   = (const float*)d_in[14];
    const float* p1_bi  = (const float*)d_in[15];
    const float* p2_g   = (const float*)d_in[16];
    const float* p2_b   = (const float*)d_in[17];
    const float* p2_w   = (const float*)d_in[18];
    const float* p2_bi  = (const float*)d_in[19];
    const float* p3_g   = (const float*)d_in[20];
    const float* p3_b   = (const float*)d_in[21];
    const float* p3_w   = (const float*)d_in[22];
    const float* p3_bi  = (const float*)d_in[23];
    const float* n2_g   = (const float*)d_in[24];
    const float* n2_b   = (const float*)d_in[25];
    const float* fc1_w  = (const float*)d_in[26];
    const float* fc1_b  = (const float*)d_in[27];
    const float* fc2_w  = (const float*)d_in[28];
    const float* fc2_b  = (const float*)d_in[29];
    float* out = (float*)d_out;

    __nv_bfloat16 *xw, *qkv, *attn, *ln2, *hid;
    __nv_bfloat16 *wt_qkv, *wt_proj, *wt_fc1, *wt_fc2;
    cudaGetSymbolAddress((void**)&xw,   gb_xw);
    cudaGetSymbolAddress((void**)&qkv,  gb_qkv);
    cudaGetSymbolAddress((void**)&attn, gb_attn);
    cudaGetSymbolAddress((void**)&ln2,  gb_ln2);
    cudaGetSymbolAddress((void**)&hid,  gb_hid);
    cudaGetSymbolAddress((void**)&wt_qkv,  gb_wt_qkv);
    cudaGetSymbolAddress((void**)&wt_proj, gb_wt_proj);
    cudaGetSymbolAddress((void**)&wt_fc1,  gb_wt_fc1);
    cudaGetSymbolAddress((void**)&wt_fc2,  gb_wt_fc2);

    static bool attr_set = false;
    if (!attr_set) {
        cudaFuncSetAttribute(attn_kernel, cudaFuncAttributeMaxDynamicSharedMemorySize,
                             ATTN_SMEM);
        cudaFuncSetAttribute(gemm_proj_ln, cudaFuncAttributeMaxDynamicSharedMemorySize,
                             PROJ_SMEM);
        attr_set = true;
    }

    // 0. weight transposes
    transpose_all<<<(TW_TOTAL + 255) / 256, 256>>>(qkv_w, proj_w, fc1_w, fc2_w);

    // 1. position-bias MLP, then full bias table
    pos_mlp_kernel<<<1, 256>>>(pp_w, pp_b, p1_g, p1_b, p1_w, p1_bi,
                               p2_g, p2_b, p2_w, p2_bi, p3_g, p3_b, p3_w, p3_bi);
    bias_build<<<(4 * HEADS * NWIN * NWIN + 255) / 256, 256>>>();

    // 2. LN1 + shift + window partition -> bf16
    ln1_kernel<<<MROWS / 8, 256>>>(x, xw, n1_g, n1_b);

    // 3. QKV GEMM -> bf16 (Q pre-scaled)
    gemm_mma<0><<<dim3(576 / 64, MROWS / 128), 256>>>(xw, wt_qkv, qkv_b, nullptr, qkv, CC, 576);

    // 4. tensor-core attention -> bf16
    attn_kernel<<<NWINDOWS, 384, ATTN_SMEM>>>(qkv, attn);

    // 5. proj + scatter + residual + LN2 (fused)
    gemm_proj_ln<<<MROWS / 128, 256, PROJ_SMEM>>>(attn, wt_proj, proj_b, x, out, ln2, n2_g, n2_b);

    // 6. FC1 + GELU -> bf16
    gemm_mma<1><<<dim3(HIDDEN / 64, MROWS / 128), 256>>>(ln2, wt_fc1, fc1_b, nullptr, hid, CC, HIDDEN);

    // 7. FC2 + residual -> fp32 out
    gemm_mma<3><<<dim3(CC / 64, MROWS / 128), 256>>>(hid, wt_fc2, fc2_b, out, out, HIDDEN, CC);
}